// round 14
// baseline (speedup 1.0000x reference)
#include <cuda_runtime.h>
#include <cuda_bf16.h>
#include <math.h>

#define Bb 2
#define Tt 2048
#define Cc 768
#define Hh 12

typedef unsigned long long ull;
typedef long long ll;

static const ll CTll  = (ll)Cc * Tt;
static const ll BTCll = (ll)Bb * Tt * Cc;

// ---------------- workspace ----------------
#define WS_XP   0LL
#define WS_TMP  3145728LL
#define WS_XBP  4718592LL
#define WS_H1P  23592960LL
#define WS_TM2P 24379392LL
#define WS_GT   25165824LL
#define WS_RIN  28311552LL   // 6 x (B,T,C) fp32: r,w,k,v,am,bm
#define WS_KL   47185920LL
#define WS_AS   50331648LL
#define WS_Y    53477376LL
#define WS_WPL  56623104LL   // weight bf16 planes
__device__ float g_ws[59080704];

#define WTOT 2359296

// ---------------- helpers ----------------
__device__ __forceinline__ void fma2(ull &d, ull a, ull b) {
    asm("fma.rn.f32x2 %0, %1, %2, %0;" : "+l"(d) : "l"(a), "l"(b));
}
__device__ __forceinline__ ull mul2(ull a, ull b) {
    ull d; asm("mul.rn.f32x2 %0, %1, %2;" : "=l"(d) : "l"(a), "l"(b)); return d;
}
__device__ __forceinline__ ull pk2(float v) {
    ull r; unsigned u = __float_as_uint(v);
    asm("mov.b64 %0, {%1, %1};" : "=l"(r) : "r"(u));
    return r;
}
__device__ __forceinline__ float lo2(ull p) { return __uint_as_float((unsigned)p); }
__device__ __forceinline__ float hi2(ull p) { return __uint_as_float((unsigned)(p >> 32)); }

__device__ __forceinline__ unsigned pack_hl(float v) {
    __nv_bfloat16 h = __float2bfloat16(v);
    float hf = __bfloat162float(h);
    __nv_bfloat16 l = __float2bfloat16(v - hf);
    return (unsigned)__bfloat16_as_ushort(h) | ((unsigned)__bfloat16_as_ushort(l) << 16);
}
__device__ __forceinline__ unsigned prmt(unsigned a, unsigned b, unsigned s) {
    unsigned d; asm("prmt.b32 %0,%1,%2,%3;" : "=r"(d) : "r"(a), "r"(b), "r"(s)); return d;
}
__device__ __forceinline__ void ldsm4(unsigned &r0, unsigned &r1, unsigned &r2, unsigned &r3,
                                      unsigned saddr) {
    asm volatile("ldmatrix.sync.aligned.m8n8.x4.shared.b16 {%0,%1,%2,%3}, [%4];"
        : "=r"(r0), "=r"(r1), "=r"(r2), "=r"(r3) : "r"(saddr));
}
__device__ __forceinline__ void mma16(float c[4], unsigned a0, unsigned a1, unsigned a2,
                                      unsigned a3, unsigned b0, unsigned b1) {
    asm volatile("mma.sync.aligned.m16n8k16.row.col.f32.bf16.bf16.f32 "
        "{%0,%1,%2,%3}, {%4,%5,%6,%7}, {%8,%9}, {%0,%1,%2,%3};"
        : "+f"(c[0]), "+f"(c[1]), "+f"(c[2]), "+f"(c[3])
        : "r"(a0), "r"(a1), "r"(a2), "r"(a3), "r"(b0), "r"(b1));
}
__device__ __forceinline__ void cpa16(void* dst, const void* src) {
    unsigned d = (unsigned)__cvta_generic_to_shared(dst);
    asm volatile("cp.async.cg.shared.global [%0], [%1], 16;" :: "r"(d), "l"(src));
}
#define CP_COMMIT asm volatile("cp.async.commit_group;")
#define CP_WAIT1  asm volatile("cp.async.wait_group 1;")

// ---------------- prep kernels ----------------
struct PrepTab {
    const float* src[19];
    int dst[19], M[19], K[19], sm[19], sk[19];
};

__global__ __launch_bounds__(256) void prep_w(__nv_bfloat16* hi, PrepTab pt) {
    int sgi = blockIdx.z;
    int idx = blockIdx.x * 256 + threadIdx.x;
    int MK = pt.M[sgi] * pt.K[sgi];
    if (idx >= MK) return;
    int k = idx % pt.K[sgi];
    int m = idx / pt.K[sgi];
    float v = pt.src[sgi][(ll)m * pt.sm[sgi] + (ll)k * pt.sk[sgi]];
    __nv_bfloat16 h = __float2bfloat16(v);
    float hf = __bfloat162float(h);
    __nv_bfloat16 l = __float2bfloat16(v - hf);
    hi[pt.dst[sgi] + idx] = h;
    hi[WTOT + pt.dst[sgi] + idx] = l;
}

__global__ __launch_bounds__(256) void prep_x(const float* __restrict__ x,
                                              unsigned* __restrict__ xp) {
    int idx = blockIdx.x * 256 + threadIdx.x;
    int t = idx & 2047;
    int rest = idx >> 11;
    int c = rest % Cc, b = rest / Cc;
    xp[(ll)b * 1572864 + (ll)(c >> 1) * 4096 + 2 * t + (c & 1)] = pack_hl(x[idx]);
}

// ---------------- GEMM ----------------
enum { EPI_NONE = 0, EPI_TANH = 1, EPI_MIX = 2, EPI_DECAY = 3, EPI_SIG = 4 };

struct ZMap {
    ll a[12], b[12], o[12], x1[12], x2[12];
    int epi[12], Kz[12], ym[12];
};

__device__ __forceinline__ float apply_epi(float v, int epi, const float* p1,
                                           const float* x2, int m, int n, int N) {
    if (epi == EPI_TANH) {
        v = tanhf(v);
    } else if (epi == EPI_MIX) {
        v = x2[(ll)m * N + n] * (1.f + p1[m] + v);
    } else if (epi == EPI_DECAY) {
        float u = -(p1[m] + v);
        float sp = fmaxf(u, 0.f) + log1pf(expf(-fabsf(u)));
        v = expf(-expf(-sp - 0.5f));
    } else if (epi == EPI_SIG) {
        v = 1.f / (1.f + expf(-(p1[m] + v)));
    }
    return v;
}

// block tile 64 x 64, KC=32, 256 threads (8 warps: 2m x 4n), 3 CTAs/SM
__global__ __launch_bounds__(256, 3) void gemm_k(
    const __nv_bfloat16* __restrict__ Apl, ll Atot,
    const unsigned* __restrict__ Bpl,
    float* __restrict__ Ob, unsigned* __restrict__ Pb,
    int sOM, int sON, int N, int omode,
    const float* __restrict__ aux1, const float* __restrict__ aux2,
    ZMap zm)
{
    constexpr int MT = 2;
    constexpr int ABYTES = 64 * 80;
    constexpr int STG = 2 * ABYTES + 16 * 544;
    extern __shared__ char smem[];

    const int z = blockIdx.z;
    if ((int)blockIdx.y >= zm.ym[z]) return;
    const int K = zm.Kz[z];
    const __nv_bfloat16* Ahi = Apl + zm.a[z];
    const unsigned* Bg = Bpl + zm.b[z];
    const ll zo = zm.o[z];
    const float* p1 = aux1 ? aux1 + zm.x1[z] : (const float*)0;
    const float* x2 = aux2 ? aux2 + zm.x2[z] : (const float*)0;
    const int epi = zm.epi[z];

    const int tid = threadIdx.x;
    const int m0 = blockIdx.y * 64, n0 = blockIdx.x * 64;
    const int warp = tid >> 5, lane = tid & 31;
    const int qr = lane >> 2, qc = lane & 3;
    const int wm0 = (warp & 1) * 32;
    const int wn0 = (warp >> 1) * 16;
    const int rowW = 2 * N;

    unsigned sbase = (unsigned)__cvta_generic_to_shared(smem);

    auto issue = [&](int kt) {
        char* S = smem + (kt % 3) * STG;
        int k0 = kt * 32;
        {
            int am = tid >> 2, ae = (tid & 3) * 8;
            const __nv_bfloat16* s0 = Ahi + (ll)(m0 + am) * K + k0 + ae;
            char* d0 = S + am * 80 + ae * 2;
            cpa16(d0, s0);
            cpa16(d0 + ABYTES, s0 + Atot);
        }
        {
            int kp = tid >> 4, wo = (tid & 15) * 8;
            const unsigned* s = Bg + (ll)(k0 / 2 + kp) * rowW + n0 * 2 + wo;
            char* d = S + 2 * ABYTES + kp * 544 + wo * 4;
            cpa16(d, s); cpa16(d + 16, s + 4);
        }
    };

    float c[MT][2][4];
#pragma unroll
    for (int mt = 0; mt < MT; mt++)
#pragma unroll
        for (int nt = 0; nt < 2; nt++)
#pragma unroll
            for (int r = 0; r < 4; r++) c[mt][nt][r] = 0.f;

    const int nk = K >> 5;
    issue(0); CP_COMMIT;
    if (nk > 1) issue(1);
    CP_COMMIT;

    for (int kt = 0; kt < nk; kt++) {
        CP_WAIT1;
        __syncthreads();
        if (kt + 2 < nk) issue(kt + 2);
        CP_COMMIT;

        char* Sst = smem + (kt % 3) * STG;
        unsigned SAu = sbase + (kt % 3) * STG;
        char* Sb = Sst + 2 * ABYTES;

#pragma unroll
        for (int s = 0; s < 2; s++) {
            unsigned bh[2][2], bl[2][2];
#pragma unroll
            for (int nt = 0; nt < 2; nt++) {
                int n = wn0 + nt * 8 + qr;
                uint2 w01 = *(const uint2*)(Sb + (s * 8 + qc) * 544 + n * 8);
                uint2 w23 = *(const uint2*)(Sb + (s * 8 + qc + 4) * 544 + n * 8);
                bh[nt][0] = prmt(w01.x, w01.y, 0x5410); bl[nt][0] = prmt(w01.x, w01.y, 0x7632);
                bh[nt][1] = prmt(w23.x, w23.y, 0x5410); bl[nt][1] = prmt(w23.x, w23.y, 0x7632);
            }
#pragma unroll
            for (int mt = 0; mt < MT; mt++) {
                unsigned aaddr = SAu + (wm0 + mt * 16 + (lane & 15)) * 80 + (lane >> 4) * 16 + s * 32;
                unsigned h0, h1, h2, h3, l0, l1, l2, l3;
                ldsm4(h0, h1, h2, h3, aaddr);
                ldsm4(l0, l1, l2, l3, aaddr + ABYTES);
#pragma unroll
                for (int nt = 0; nt < 2; nt++) {
                    mma16(c[mt][nt], h0, h1, h2, h3, bh[nt][0], bh[nt][1]);
                    mma16(c[mt][nt], l0, l1, l2, l3, bh[nt][0], bh[nt][1]);
                    mma16(c[mt][nt], h0, h1, h2, h3, bl[nt][0], bl[nt][1]);
                }
            }
        }
    }

    const bool use_tr = (omode == 0) && (sON != 1);
    if (use_tr) __syncthreads();
    float* Tf = (float*)smem;

#pragma unroll
    for (int mt = 0; mt < MT; mt++) {
#pragma unroll
        for (int nt = 0; nt < 2; nt++) {
            int mL = wm0 + mt * 16 + qr;
            int nL = wn0 + nt * 8 + qc * 2;
            int mA = m0 + mL;
            int nA = n0 + nL;
            float v0 = apply_epi(c[mt][nt][0], epi, p1, x2, mA, nA, N);
            float v1 = apply_epi(c[mt][nt][1], epi, p1, x2, mA, nA + 1, N);
            float v2 = apply_epi(c[mt][nt][2], epi, p1, x2, mA + 8, nA, N);
            float v3 = apply_epi(c[mt][nt][3], epi, p1, x2, mA + 8, nA + 1, N);
            if (omode == 0) {
                if (sON == 1) {
                    float* O = Ob + zo;
                    *(float2*)(O + (ll)mA * sOM + nA)       = make_float2(v0, v1);
                    *(float2*)(O + (ll)(mA + 8) * sOM + nA) = make_float2(v2, v3);
                } else {
                    Tf[nL * 68 + mL]           = v0;
                    Tf[(nL + 1) * 68 + mL]     = v1;
                    Tf[nL * 68 + mL + 8]       = v2;
                    Tf[(nL + 1) * 68 + mL + 8] = v3;
                }
            } else {
                unsigned* P = Pb + zo;
                ll r0 = (ll)(mA >> 1) * rowW + (mA & 1);
                ll r1 = r0 + (ll)4 * rowW;
                P[r0 + 2 * nA]       = pack_hl(v0);
                P[r0 + 2 * (nA + 1)] = pack_hl(v1);
                P[r1 + 2 * nA]       = pack_hl(v2);
                P[r1 + 2 * (nA + 1)] = pack_hl(v3);
            }
        }
    }

    if (use_tr) {
        __syncthreads();
        float* O = Ob + zo;
#pragma unroll
        for (int p = 0; p < 4; p++) {
            int row = p * 16 + (tid >> 4);
            int c4 = (tid & 15) * 4;
            float4 v = *(float4*)&Tf[row * 68 + c4];
            *(float4*)(O + (ll)(n0 + row) * sON + m0 + c4) = v;
        }
    }
}

// ---------------- E1 ----------------
__global__ __launch_bounds__(256) void e1_k(
    const float* __restrict__ kc, const float* __restrict__ kl,
    const float* __restrict__ asig, float* __restrict__ am, float* __restrict__ bm)
{
    int gw = (int)((blockIdx.x * blockDim.x + threadIdx.x) >> 5);
    int lane = threadIdx.x & 31;
    ll base = (ll)gw * 64;
    float k1 = kc[base + lane]      + kl[base + lane];
    float k2 = kc[base + lane + 32] + kl[base + lane + 32];
    float ss = k1 * k1 + k2 * k2;
#pragma unroll
    for (int o = 16; o; o >>= 1) ss += __shfl_xor_sync(0xffffffffu, ss, o);
    float inv = 1.f / fmaxf(sqrtf(ss), 1e-12f);
    float n1 = k1 * inv, n2 = k2 * inv;
    am[base + lane]      = -n1;
    am[base + lane + 32] = -n2;
    bm[base + lane]      = n1 * asig[base + lane];
    bm[base + lane + 32] = n2 * asig[base + lane + 32];
}

// ---------------- WKV7: RS=4, 3-stage ring, full-step LDG->STS slack ----------------
#define RS 4
__global__ __launch_bounds__(64) void wkv7_k(const float* __restrict__ rin, float* __restrict__ y)
{
    int blk = blockIdx.x;
    int rs = blk & 3;
    int bh = blk >> 2;
    int b = bh / Hh, h = bh % Hh;
    ll base = (ll)b * Tt * Cc + (ll)h * 64;

    int tid = threadIdx.x;
    int lr = tid >> 2, jc = tid & 3;
    int i = rs * 16 + lr;
    int jb = jc << 4;

    __shared__ __align__(16) float sh[3][384];

    // preload t=0,1
#pragma unroll
    for (int tt = 0; tt < 2; tt++) {
        ll off = base + (ll)tt * Cc;
#pragma unroll
        for (int q = 0; q < 6; q++)
            sh[tt][q * 64 + tid] = rin[(ll)q * BTCll + off + tid];
    }
    // load pfB = data(t=2)
    float pfB[6];
    {
        ll off = base + 2LL * Cc;
#pragma unroll
        for (int q = 0; q < 6; q++)
            pfB[q] = (2 < Tt) ? rin[(ll)q * BTCll + off + tid] : 0.f;
    }
    __syncthreads();

    ull S2[8];
#pragma unroll
    for (int u = 0; u < 8; u++) S2[u] = 0ull;
    float sa = 0.f;

    for (int t = 0; t < Tt; t++) {
        // 1. store pfB (data t+2) into ring buffer (t+2)%3 — full step of LDG slack behind it
        {
            float* sd = sh[(t + 2) % 3];
#pragma unroll
            for (int q = 0; q < 6; q++) sd[q * 64 + tid] = pfB[q];
        }
        // 2. issue loads for data t+3 (consumed by STS at step t+1)
        if (t + 3 < Tt) {
            ll off = base + (ll)(t + 3) * Cc;
#pragma unroll
            for (int q = 0; q < 6; q++)
                pfB[q] = rin[(ll)q * BTCll + off + tid];
        } else {
#pragma unroll
            for (int q = 0; q < 6; q++) pfB[q] = 0.f;
        }

        // 3. compute
        const float* sb = sh[t % 3];
        const float* sn = sh[(t + 1) % 3];
        float vi = sb[3 * 64 + i];
        ull vi2 = pk2(vi), sa2 = pk2(sa);

        const ulonglong2* wp = (const ulonglong2*)(sb + 1 * 64 + jb);
        const ulonglong2* kp = (const ulonglong2*)(sb + 2 * 64 + jb);
        const ulonglong2* bp = (const ulonglong2*)(sb + 5 * 64 + jb);
        const ulonglong2* rp = (const ulonglong2*)(sb + 0 * 64 + jb);

#pragma unroll
        for (int q = 0; q < 4; q++) {
            ulonglong2 wv = wp[q], kv = kp[q], bv = bp[q];
            ull d0 = mul2(vi2, kv.x);
            fma2(d0, sa2, bv.x);
            fma2(d0, S2[2 * q], wv.x);
            S2[2 * q] = d0;
            ull d1 = mul2(vi2, kv.y);
            fma2(d1, sa2, bv.y);
            fma2(d1, S2[2 * q + 1], wv.y);
            S2[2 * q + 1] = d1;
        }

        ull ya = 0ull, yb = 0ull;
#pragma unroll
        for (int q = 0; q < 4; q++) {
            ulonglong2 rv = rp[q];
            fma2(ya, S2[2 * q], rv.x);
            fma2(yb, S2[2 * q + 1], rv.y);
        }

        // sa partials for t+1 (a(t+1) already staged in sn)
        const ulonglong2* ap = (const ulonglong2*)(sn + 4 * 64 + jb);
        ull za = 0ull, zb = 0ull;
#pragma unroll
        for (int q = 0; q < 4; q++) {
            ulonglong2 av = ap[q];
            fma2(za, S2[2 * q], av.x);
            fma2(zb, S2[2 * q + 1], av.y);
        }

        // 4. barrier: makes step-t STS visible for t+1, protects ring reuse
        __syncthreads();

        // 5. reductions + output (off the staging path)
        float yv = (lo2(ya) + hi2(ya)) + (lo2(yb) + hi2(yb));
        float sv = (lo2(za) + hi2(za)) + (lo2(zb) + hi2(zb));
        yv += __shfl_xor_sync(0xffffffffu, yv, 1);
        sv += __shfl_xor_sync(0xffffffffu, sv, 1);
        yv += __shfl_xor_sync(0xffffffffu, yv, 2);
        sv += __shfl_xor_sync(0xffffffffu, sv, 2);
        sa = sv;
        if (jc == 0)
            y[base + (ll)t * Cc + i] = yv;
    }
}

// ---------------- E2 (writes YG planes) ----------------
__global__ __launch_bounds__(768) void e2_k(
    const float* __restrict__ y,
    const float* __restrict__ rr, const float* __restrict__ kk, const float* __restrict__ vv,
    const float* __restrict__ gg, const float* __restrict__ faaaa,
    const float* __restrict__ lnw, unsigned* __restrict__ ygp)
{
    int bt = blockIdx.x;
    int b = bt >> 11, t = bt & 2047;
    ll base = (ll)bt * Cc;
    int c = threadIdx.x;
    int w = c >> 5, h = c >> 6, j = c & 63, lane = c & 31;
    float yv = y[base + c];
    float rv = rr[base + c], kv = kk[base + c], vV = vv[base + c];
    float s1 = yv * yv;
    float s2 = rv * kv * faaaa[h * 64 + j];
#pragma unroll
    for (int o = 16; o; o >>= 1) {
        s1 += __shfl_xor_sync(0xffffffffu, s1, o);
        s2 += __shfl_xor_sync(0xffffffffu, s2, o);
    }
    __shared__ float sh1[24], sh2[24];
    if (lane == 0) { sh1[w] = s1; sh2[w] = s2; }
    __syncthreads();
    float tot = 0.f;
#pragma unroll
    for (int q = 0; q < 24; q++) tot += sh1[q];
    float scale = rsqrtf(tot * (1.f / 768.f) + 1e-5f);
    float rk = sh2[h * 2] + sh2[h * 2 + 1];
    float yo = (yv * scale * lnw[c] + rk * vV) * gg[base + c];
    ygp[(ll)b * 1572864 + (ll)(c >> 1) * 4096 + 2 * t + (c & 1)] = pack_hl(yo);
}

// ---------------- launch ----------------
#define SMEM64 (3 * (2 * 64 * 80 + 16 * 544))

extern "C" void kernel_launch(void* const* d_in, const int* in_sizes, int n_in,
                              void* d_out, int out_size)
{
    (void)in_sizes; (void)n_in; (void)out_size;
    const float* x       = (const float*)d_in[0];
    const float* tmaa_r  = (const float*)d_in[2];
    const float* tmaa_w  = (const float*)d_in[3];
    const float* tmaa_k  = (const float*)d_in[4];
    const float* tmaa_v  = (const float*)d_in[5];
    const float* tmaa_a  = (const float*)d_in[6];
    const float* tmaa_g  = (const float*)d_in[7];
    const float* tdecay  = (const float*)d_in[8];
    const float* faaaa   = (const float*)d_in[9];
    const float* taaaaa  = (const float*)d_in[10];
    const float* maa_w1  = (const float*)d_in[11];
    const float* maa_w2  = (const float*)d_in[12];
    const float* dec_w1  = (const float*)d_in[13];
    const float* dec_w2  = (const float*)d_in[14];
    const float* aaa_w1  = (const float*)d_in[15];
    const float* aaa_w2  = (const float*)d_in[16];
    const float* kkk_w1  = (const float*)d_in[17];
    const float* kkk_w2  = (const float*)d_in[18];
    const float* gate_w1 = (const float*)d_in[19];
    const float* gate_w2 = (const float*)d_in[20];
    const float* w_key   = (const float*)d_in[21];
    const float* w_val   = (const float*)d_in[22];
    const float* w_rec   = (const float*)d_in[23];
    const float* w_out   = (const float*)d_in[24];
    const float* lnw     = (const float*)d_in[25];
    float* out = (float*)d_out;

    static int attr_done = 0;
    if (!attr_done) {
        cudaFuncSetAttribute(gemm_k, cudaFuncAttributeMaxDynamicSharedMemorySize, SMEM64);
        attr_done = 1;
    }

    float* ws = 0;
    cudaGetSymbolAddress((void**)&ws, g_ws);

    unsigned* XP   = (unsigned*)(ws + WS_XP);
    unsigned* TMP  = (unsigned*)(ws + WS_TMP);
    unsigned* XBP  = (unsigned*)(ws + WS_XBP);
    float* RIN = ws + WS_RIN;
    float* Y   = ws + WS_Y;
    __nv_bfloat16* WPL = (__nv_bfloat16*)(ws + WS_WPL);

    // ---- weight prep ----
    {
        PrepTab pt;
        int i = 0;
        auto seg = [&](const float* s, int d, int M, int K, int sm, int sk) {
            pt.src[i] = s; pt.dst[i] = d; pt.M[i] = M; pt.K[i] = K; pt.sm[i] = sm; pt.sk[i] = sk; i++;
        };
        seg(maa_w1, 0, 384, 768, 768, 1);
        for (int n = 0; n < 6; n++) seg(maa_w2 + n * 49152, 294912 + n * 49152, 768, 64, 1, 768);
        seg(w_rec, 589824, 768, 384, 384, 1);
        seg(w_key, 884736, 768, 384, 384, 1);
        seg(w_val, 1179648, 768, 384, 384, 1);
        seg(dec_w1, 1474560, 64, 768, 768, 1);
        seg(kkk_w1, 1523712, 64, 768, 768, 1);
        seg(aaa_w1, 1572864, 64, 768, 768, 1);
        seg(dec_w2, 1622016, 768, 64, 64, 1);
        seg(kkk_w2, 1671168, 768, 64, 64, 1);
        seg(aaa_w2, 1720320, 768, 64, 64, 1);
        seg(gate_w1, 1769472, 192, 768, 768, 1);
        seg(gate_w2, 1916928, 768, 192, 192, 1);
        seg(w_out, 2064384, 768, 384, 384, 1);
        prep_w<<<dim3(1152, 1, 19), 256>>>(WPL, pt);
    }
    prep_x<<<(Bb * Cc * Tt) / 256, 256>>>(x, XP);

    // G1) TM planes = tanh(maa_w1 @ x): M=384, K=768
    {
        ZMap zm = {};
        for (int b = 0; b < 2; b++) {
            zm.b[b] = (ll)b * 1572864;
            zm.o[b] = (ll)b * 786432;
            zm.epi[b] = EPI_TANH;
            zm.Kz[b] = 768; zm.ym[b] = 6;
        }
        gemm_k<<<dim3(32, 6, 2), 256, SMEM64>>>(WPL, WTOT, XP, 0, TMP,
                                                0, 0, 2048, 1, 0, 0, zm);
    }

    // G2) MIX -> XB planes: z=n*2+b, M=768, K=64
    {
        ZMap zm = {};
        const float* tmaas[6] = {tmaa_r, tmaa_w, tmaa_k, tmaa_v, tmaa_a, tmaa_g};
        for (int n = 0; n < 6; n++)
            for (int b = 0; b < 2; b++) {
                int z = n * 2 + b;
                zm.a[z]  = 294912 + (ll)n * 49152;
                zm.b[z]  = (ll)b * 786432 + (ll)n * 131072;
                zm.o[z]  = ((ll)n * 2 + b) * 1572864;
                zm.x1[z] = (ll)(tmaas[n] - tmaa_r);
                zm.x2[z] = (ll)b * CTll;
                zm.epi[z] = EPI_MIX;
                zm.Kz[z] = 64; zm.ym[z] = 12;
            }
        gemm_k<<<dim3(32, 12, 12), 256, SMEM64>>>(WPL, WTOT, TMP, 0, XBP,
                                                  0, 0, 2048, 1, tmaa_r, x, zm);
    }

    // G3) convs (r,k,v) -> RIN fp32: z=q*4+g*2+b, M=384, K=384 (transposed store)
    {
        ZMap zm = {};
        const int xbi[3] = {0, 2, 3};
        const int rio[3] = {0, 2, 3};
        for (int q = 0; q < 3; q++)
            for (int g = 0; g < 2; g++)
                for (int b = 0; b < 2; b++) {
                    int z = q * 4 + g * 2 + b;
                    zm.a[z] = 589824 + (ll)q * 294912 + (ll)g * 147456;
                    zm.b[z] = ((ll)xbi[q] * 2 + b) * 1572864 + (ll)g * 786432;
                    zm.o[z] = (ll)rio[q] * BTCll + (ll)b * CTll + g * 384;
                    zm.epi[z] = EPI_NONE;
                    zm.Kz[z] = 384; zm.ym[z] = 6;
                }
        gemm_k<<<dim3(32, 6, 12), 256, SMEM64>>>(WPL, WTOT, XBP, RIN, 0,
                                                 1, Cc, 2048, 0, 0, 0, zm);
    }

    // G45) lora stage1 (dec,kkk,aaa) + gate stage1, merged: K=768
    {
        ZMap zm = {};
        const int sl[3] = {1, 2, 4};
        for (int q = 0; q < 3; q++)
            for (int b = 0; b < 2; b++) {
                int z = q * 2 + b;
                zm.a[z] = 1474560 + (ll)q * 49152;
                zm.b[z] = ((ll)sl[q] * 2 + b) * 1572864;
                zm.o[z] = WS_H1P + ((ll)q * 2 + b) * 131072;
                zm.epi[z] = EPI_TANH;
                zm.Kz[z] = 768; zm.ym[z] = 1;
            }
        for (int b = 0; b < 2; b++) {
            int z = 6 + b;
            zm.a[z] = 1769472;
            zm.b[z] = (10LL + b) * 1572864;
            zm.o[z] = WS_TM2P + (ll)b * 393216;
            zm.epi[z] = EPI_TANH;
            zm.Kz[z] = 768; zm.ym[z] = 3;
        }
        gemm_k<<<dim3(32, 3, 8), 256, SMEM64>>>(WPL, WTOT, XBP, 0, (unsigned*)ws,
                                                0, 0, 2048, 1, 0, 0, zm);
    }

    // G67) lora stage2 (wdec, KL, AS) + gate stage2, merged (transposed store)
    {
        ZMap zm = {};
        ll od[3] = {WS_RIN + BTCll, WS_KL, WS_AS};
        const int ep[3] = {EPI_DECAY, EPI_NONE, EPI_SIG};
        ll xd[3] = {0, 0, (ll)(taaaaa - tdecay)};
        for (int q = 0; q < 3; q++)
            for (int b = 0; b < 2; b++) {
                int z = q * 2 + b;
                zm.a[z]  = 1622016 + (ll)q * 49152;
                zm.b[z]  = WS_H1P + ((ll)q * 2 + b) * 131072;
                zm.o[z]  = od[q] + (ll)b * CTll;
                zm.x1[z] = xd[q];
                zm.epi[z] = ep[q];
                zm.Kz[z] = 64; zm.ym[z] = 12;
            }
        for (int b = 0; b < 2; b++) {
            int z = 6 + b;
            zm.a[z] = 1916928;
            zm.b[z] = WS_TM2P + (ll)b * 393216;
            zm.o[z] = WS_GT + (ll)b * CTll;
            zm.epi[z] = EPI_NONE;
            zm.Kz[z] = 192; zm.ym[z] = 12;
        }
        gemm_k<<<dim3(32, 12, 8), 256, SMEM64>>>(WPL, WTOT, (unsigned*)ws, ws, 0,
                                                 1, Cc, 2048, 0, tdecay, 0, zm);
    }

    // E1
    e1_k<<<(Bb * Tt * Hh) / 8, 256>>>(RIN + 2 * BTCll, ws + WS_KL, ws + WS_AS,
                                      RIN + 4 * BTCll, RIN + 5 * BTCll);

    // WKV7
    wkv7_k<<<Bb * Hh * RS, 64>>>(RIN, Y);

    // E2 -> YG planes (reuse XP)
    e2_k<<<Bb * Tt, 768>>>(Y, RIN, RIN + 2 * BTCll, RIN + 3 * BTCll,
                           ws + WS_GT, faaaa, lnw, XP);

    // G11) output conv: z=g*2+b, M=384, K=384, out fp32 (B,C,T)
    {
        ZMap zm = {};
        for (int g = 0; g < 2; g++)
            for (int b = 0; b < 2; b++) {
                int z = g * 2 + b;
                zm.a[z] = 2064384 + (ll)g * 147456;
                zm.b[z] = (ll)b * 1572864 + (ll)g * 786432;
                zm.o[z] = (ll)b * CTll + (ll)g * 384 * Tt;
                zm.epi[z] = EPI_NONE;
                zm.Kz[z] = 384; zm.ym[z] = 6;
            }
        gemm_k<<<dim3(32, 6, 4), 256, SMEM64>>>(WPL, WTOT, XP, out, 0,
                                                Tt, 1, 2048, 0, 0, 0, zm);
    }
}

// round 15
// speedup vs baseline: 1.9498x; 1.9498x over previous
#include <cuda_runtime.h>
#include <cuda_bf16.h>
#include <math.h>

#define Bb 2
#define Tt 2048
#define Cc 768
#define Hh 12

typedef unsigned long long ull;
typedef long long ll;

static const ll CTll  = (ll)Cc * Tt;
static const ll BTCll = (ll)Bb * Tt * Cc;

// ---------------- workspace ----------------
#define WS_XP   0LL
#define WS_TMP  3145728LL
#define WS_XBP  4718592LL
#define WS_H1P  23592960LL
#define WS_TM2P 24379392LL
#define WS_GT   25165824LL
#define WS_RIN  28311552LL   // 6 x (B,T,C) fp32: r,w,k,v,am,bm
#define WS_KL   47185920LL
#define WS_AS   50331648LL
#define WS_Y    53477376LL
#define WS_WPL  56623104LL   // weight bf16 planes
__device__ float g_ws[59080704];

#define WTOT 2359296

// ---------------- helpers ----------------
__device__ __forceinline__ void fma2(ull &d, ull a, ull b) {
    asm("fma.rn.f32x2 %0, %1, %2, %0;" : "+l"(d) : "l"(a), "l"(b));
}
__device__ __forceinline__ ull mul2(ull a, ull b) {
    ull d; asm("mul.rn.f32x2 %0, %1, %2;" : "=l"(d) : "l"(a), "l"(b)); return d;
}
__device__ __forceinline__ ull pk2(float v) {
    ull r; unsigned u = __float_as_uint(v);
    asm("mov.b64 %0, {%1, %1};" : "=l"(r) : "r"(u));
    return r;
}
__device__ __forceinline__ float lo2(ull p) { return __uint_as_float((unsigned)p); }
__device__ __forceinline__ float hi2(ull p) { return __uint_as_float((unsigned)(p >> 32)); }

__device__ __forceinline__ unsigned pack_hl(float v) {
    __nv_bfloat16 h = __float2bfloat16(v);
    float hf = __bfloat162float(h);
    __nv_bfloat16 l = __float2bfloat16(v - hf);
    return (unsigned)__bfloat16_as_ushort(h) | ((unsigned)__bfloat16_as_ushort(l) << 16);
}
__device__ __forceinline__ unsigned prmt(unsigned a, unsigned b, unsigned s) {
    unsigned d; asm("prmt.b32 %0,%1,%2,%3;" : "=r"(d) : "r"(a), "r"(b), "r"(s)); return d;
}
__device__ __forceinline__ void ldsm4(unsigned &r0, unsigned &r1, unsigned &r2, unsigned &r3,
                                      unsigned saddr) {
    asm volatile("ldmatrix.sync.aligned.m8n8.x4.shared.b16 {%0,%1,%2,%3}, [%4];"
        : "=r"(r0), "=r"(r1), "=r"(r2), "=r"(r3) : "r"(saddr));
}
__device__ __forceinline__ void mma16(float c[4], unsigned a0, unsigned a1, unsigned a2,
                                      unsigned a3, unsigned b0, unsigned b1) {
    asm volatile("mma.sync.aligned.m16n8k16.row.col.f32.bf16.bf16.f32 "
        "{%0,%1,%2,%3}, {%4,%5,%6,%7}, {%8,%9}, {%0,%1,%2,%3};"
        : "+f"(c[0]), "+f"(c[1]), "+f"(c[2]), "+f"(c[3])
        : "r"(a0), "r"(a1), "r"(a2), "r"(a3), "r"(b0), "r"(b1));
}
__device__ __forceinline__ void cpa16(void* dst, const void* src) {
    unsigned d = (unsigned)__cvta_generic_to_shared(dst);
    asm volatile("cp.async.cg.shared.global [%0], [%1], 16;" :: "r"(d), "l"(src));
}
__device__ __forceinline__ void cpa4(void* dst, const void* src) {
    unsigned d = (unsigned)__cvta_generic_to_shared(dst);
    asm volatile("cp.async.ca.shared.global [%0], [%1], 4;" :: "r"(d), "l"(src));
}
#define CP_COMMIT asm volatile("cp.async.commit_group;")
#define CP_WAIT1  asm volatile("cp.async.wait_group 1;")
#define CP_WAIT0  asm volatile("cp.async.wait_group 0;")

// ---------------- prep kernels ----------------
struct PrepTab {
    const float* src[19];
    int dst[19], M[19], K[19], sm[19], sk[19];
};

__global__ __launch_bounds__(256) void prep_w(__nv_bfloat16* hi, PrepTab pt) {
    int sgi = blockIdx.z;
    int idx = blockIdx.x * 256 + threadIdx.x;
    int MK = pt.M[sgi] * pt.K[sgi];
    if (idx >= MK) return;
    int k = idx % pt.K[sgi];
    int m = idx / pt.K[sgi];
    float v = pt.src[sgi][(ll)m * pt.sm[sgi] + (ll)k * pt.sk[sgi]];
    __nv_bfloat16 h = __float2bfloat16(v);
    float hf = __bfloat162float(h);
    __nv_bfloat16 l = __float2bfloat16(v - hf);
    hi[pt.dst[sgi] + idx] = h;
    hi[WTOT + pt.dst[sgi] + idx] = l;
}

__global__ __launch_bounds__(256) void prep_x(const float* __restrict__ x,
                                              unsigned* __restrict__ xp) {
    int idx = blockIdx.x * 256 + threadIdx.x;
    int t = idx & 2047;
    int rest = idx >> 11;
    int c = rest % Cc, b = rest / Cc;
    xp[(ll)b * 1572864 + (ll)(c >> 1) * 4096 + 2 * t + (c & 1)] = pack_hl(x[idx]);
}

// ---------------- GEMM ----------------
enum { EPI_NONE = 0, EPI_TANH = 1, EPI_MIX = 2, EPI_DECAY = 3, EPI_SIG = 4 };

struct ZMap {
    ll a[12], b[12], o[12], x1[12], x2[12];
    int epi[12], Kz[12], ym[12];
};

__device__ __forceinline__ float apply_epi(float v, int epi, const float* p1,
                                           const float* x2, int m, int n, int N) {
    if (epi == EPI_TANH) {
        v = tanhf(v);
    } else if (epi == EPI_MIX) {
        v = x2[(ll)m * N + n] * (1.f + p1[m] + v);
    } else if (epi == EPI_DECAY) {
        float u = -(p1[m] + v);
        float sp = fmaxf(u, 0.f) + log1pf(expf(-fabsf(u)));
        v = expf(-expf(-sp - 0.5f));
    } else if (epi == EPI_SIG) {
        v = 1.f / (1.f + expf(-(p1[m] + v)));
    }
    return v;
}

// block tile 64 x 64, KC=32, 256 threads (8 warps: 2m x 4n), 3 CTAs/SM
__global__ __launch_bounds__(256, 3) void gemm_k(
    const __nv_bfloat16* __restrict__ Apl, ll Atot,
    const unsigned* __restrict__ Bpl,
    float* __restrict__ Ob, unsigned* __restrict__ Pb,
    int sOM, int sON, int N, int omode,
    const float* __restrict__ aux1, const float* __restrict__ aux2,
    ZMap zm)
{
    constexpr int MT = 2;
    constexpr int ABYTES = 64 * 80;
    constexpr int STG = 2 * ABYTES + 16 * 544;
    extern __shared__ char smem[];

    const int z = blockIdx.z;
    if ((int)blockIdx.y >= zm.ym[z]) return;
    const int K = zm.Kz[z];
    const __nv_bfloat16* Ahi = Apl + zm.a[z];
    const unsigned* Bg = Bpl + zm.b[z];
    const ll zo = zm.o[z];
    const float* p1 = aux1 ? aux1 + zm.x1[z] : (const float*)0;
    const float* x2 = aux2 ? aux2 + zm.x2[z] : (const float*)0;
    const int epi = zm.epi[z];

    const int tid = threadIdx.x;
    const int m0 = blockIdx.y * 64, n0 = blockIdx.x * 64;
    const int warp = tid >> 5, lane = tid & 31;
    const int qr = lane >> 2, qc = lane & 3;
    const int wm0 = (warp & 1) * 32;
    const int wn0 = (warp >> 1) * 16;
    const int rowW = 2 * N;

    unsigned sbase = (unsigned)__cvta_generic_to_shared(smem);

    auto issue = [&](int kt) {
        char* S = smem + (kt % 3) * STG;
        int k0 = kt * 32;
        {
            int am = tid >> 2, ae = (tid & 3) * 8;
            const __nv_bfloat16* s0 = Ahi + (ll)(m0 + am) * K + k0 + ae;
            char* d0 = S + am * 80 + ae * 2;
            cpa16(d0, s0);
            cpa16(d0 + ABYTES, s0 + Atot);
        }
        {
            int kp = tid >> 4, wo = (tid & 15) * 8;
            const unsigned* s = Bg + (ll)(k0 / 2 + kp) * rowW + n0 * 2 + wo;
            char* d = S + 2 * ABYTES + kp * 544 + wo * 4;
            cpa16(d, s); cpa16(d + 16, s + 4);
        }
    };

    float c[MT][2][4];
#pragma unroll
    for (int mt = 0; mt < MT; mt++)
#pragma unroll
        for (int nt = 0; nt < 2; nt++)
#pragma unroll
            for (int r = 0; r < 4; r++) c[mt][nt][r] = 0.f;

    const int nk = K >> 5;
    issue(0); CP_COMMIT;
    if (nk > 1) issue(1);
    CP_COMMIT;

    for (int kt = 0; kt < nk; kt++) {
        CP_WAIT1;
        __syncthreads();
        if (kt + 2 < nk) issue(kt + 2);
        CP_COMMIT;

        char* Sst = smem + (kt % 3) * STG;
        unsigned SAu = sbase + (kt % 3) * STG;
        char* Sb = Sst + 2 * ABYTES;

#pragma unroll
        for (int s = 0; s < 2; s++) {
            unsigned bh[2][2], bl[2][2];
#pragma unroll
            for (int nt = 0; nt < 2; nt++) {
                int n = wn0 + nt * 8 + qr;
                uint2 w01 = *(const uint2*)(Sb + (s * 8 + qc) * 544 + n * 8);
                uint2 w23 = *(const uint2*)(Sb + (s * 8 + qc + 4) * 544 + n * 8);
                bh[nt][0] = prmt(w01.x, w01.y, 0x5410); bl[nt][0] = prmt(w01.x, w01.y, 0x7632);
                bh[nt][1] = prmt(w23.x, w23.y, 0x5410); bl[nt][1] = prmt(w23.x, w23.y, 0x7632);
            }
#pragma unroll
            for (int mt = 0; mt < MT; mt++) {
                unsigned aaddr = SAu + (wm0 + mt * 16 + (lane & 15)) * 80 + (lane >> 4) * 16 + s * 32;
                unsigned h0, h1, h2, h3, l0, l1, l2, l3;
                ldsm4(h0, h1, h2, h3, aaddr);
                ldsm4(l0, l1, l2, l3, aaddr + ABYTES);
#pragma unroll
                for (int nt = 0; nt < 2; nt++) {
                    mma16(c[mt][nt], h0, h1, h2, h3, bh[nt][0], bh[nt][1]);
                    mma16(c[mt][nt], l0, l1, l2, l3, bh[nt][0], bh[nt][1]);
                    mma16(c[mt][nt], h0, h1, h2, h3, bl[nt][0], bl[nt][1]);
                }
            }
        }
    }

    const bool use_tr = (omode == 0) && (sON != 1);
    if (use_tr) __syncthreads();
    float* Tf = (float*)smem;

#pragma unroll
    for (int mt = 0; mt < MT; mt++) {
#pragma unroll
        for (int nt = 0; nt < 2; nt++) {
            int mL = wm0 + mt * 16 + qr;
            int nL = wn0 + nt * 8 + qc * 2;
            int mA = m0 + mL;
            int nA = n0 + nL;
            float v0 = apply_epi(c[mt][nt][0], epi, p1, x2, mA, nA, N);
            float v1 = apply_epi(c[mt][nt][1], epi, p1, x2, mA, nA + 1, N);
            float v2 = apply_epi(c[mt][nt][2], epi, p1, x2, mA + 8, nA, N);
            float v3 = apply_epi(c[mt][nt][3], epi, p1, x2, mA + 8, nA + 1, N);
            if (omode == 0) {
                if (sON == 1) {
                    float* O = Ob + zo;
                    *(float2*)(O + (ll)mA * sOM + nA)       = make_float2(v0, v1);
                    *(float2*)(O + (ll)(mA + 8) * sOM + nA) = make_float2(v2, v3);
                } else {
                    Tf[nL * 68 + mL]           = v0;
                    Tf[(nL + 1) * 68 + mL]     = v1;
                    Tf[nL * 68 + mL + 8]       = v2;
                    Tf[(nL + 1) * 68 + mL + 8] = v3;
                }
            } else {
                unsigned* P = Pb + zo;
                ll r0 = (ll)(mA >> 1) * rowW + (mA & 1);
                ll r1 = r0 + (ll)4 * rowW;
                P[r0 + 2 * nA]       = pack_hl(v0);
                P[r0 + 2 * (nA + 1)] = pack_hl(v1);
                P[r1 + 2 * nA]       = pack_hl(v2);
                P[r1 + 2 * (nA + 1)] = pack_hl(v3);
            }
        }
    }

    if (use_tr) {
        __syncthreads();
        float* O = Ob + zo;
#pragma unroll
        for (int p = 0; p < 4; p++) {
            int row = p * 16 + (tid >> 4);
            int c4 = (tid & 15) * 4;
            float4 v = *(float4*)&Tf[row * 68 + c4];
            *(float4*)(O + (ll)(n0 + row) * sON + m0 + c4) = v;
        }
    }
}

// ---------------- E1 ----------------
__global__ __launch_bounds__(256) void e1_k(
    const float* __restrict__ kc, const float* __restrict__ kl,
    const float* __restrict__ asig, float* __restrict__ am, float* __restrict__ bm)
{
    int gw = (int)((blockIdx.x * blockDim.x + threadIdx.x) >> 5);
    int lane = threadIdx.x & 31;
    ll base = (ll)gw * 64;
    float k1 = kc[base + lane]      + kl[base + lane];
    float k2 = kc[base + lane + 32] + kl[base + lane + 32];
    float ss = k1 * k1 + k2 * k2;
#pragma unroll
    for (int o = 16; o; o >>= 1) ss += __shfl_xor_sync(0xffffffffu, ss, o);
    float inv = 1.f / fmaxf(sqrtf(ss), 1e-12f);
    float n1 = k1 * inv, n2 = k2 * inv;
    am[base + lane]      = -n1;
    am[base + lane + 32] = -n2;
    bm[base + lane]      = n1 * asig[base + lane];
    bm[base + lane + 32] = n2 * asig[base + lane + 32];
}

// ---------------- WKV7: RS=4, cp.async 4-buffer ring (3 steps ahead) ----------------
#define RS 4
__global__ __launch_bounds__(64) void wkv7_k(const float* __restrict__ rin, float* __restrict__ y)
{
    int blk = blockIdx.x;
    int rs = blk & 3;
    int bh = blk >> 2;
    int b = bh / Hh, h = bh % Hh;
    ll base = (ll)b * Tt * Cc + (ll)h * 64;

    int tid = threadIdx.x;
    int lr = tid >> 2, jc = tid & 3;
    int i = rs * 16 + lr;
    int jb = jc << 4;

    __shared__ __align__(16) float sh[4][384];

    // async stage of step tt into ring buffer tt&3 (one 4B cp per vector)
    auto stage = [&](int tt) {
        float* sd = sh[tt & 3];
        ll off = base + (ll)tt * Cc;
#pragma unroll
        for (int q = 0; q < 6; q++)
            cpa4(&sd[q * 64 + tid], &rin[(ll)q * BTCll + off + tid]);
        CP_COMMIT;
    };

    stage(0);
    stage(1);
    stage(2);

    ull S2[8];
#pragma unroll
    for (int u = 0; u < 8; u++) S2[u] = 0ull;
    float sa = 0.f;

    for (int t = 0; t < Tt; t++) {
        // groups t and t+1 must be complete; newest (t+2) may stay in flight
        if (t + 3 < Tt) { CP_WAIT1; } else { CP_WAIT0; }
        __syncthreads();               // visibility + fences step t-1 reads before buffer reuse
        if (t + 3 < Tt) stage(t + 3);  // writes (t+3)&3 == (t-1)&3, safe after barrier

        const float* sb = sh[t & 3];
        const float* sn = sh[(t + 1) & 3];
        float vi = sb[3 * 64 + i];
        ull vi2 = pk2(vi), sa2 = pk2(sa);

        const ulonglong2* wp = (const ulonglong2*)(sb + 1 * 64 + jb);
        const ulonglong2* kp = (const ulonglong2*)(sb + 2 * 64 + jb);
        const ulonglong2* bp = (const ulonglong2*)(sb + 5 * 64 + jb);
        const ulonglong2* rp = (const ulonglong2*)(sb + 0 * 64 + jb);

        // S = S*w + sa*b + vi*k
#pragma unroll
        for (int q = 0; q < 4; q++) {
            ulonglong2 wv = wp[q], kv = kp[q], bv = bp[q];
            ull d0 = mul2(vi2, kv.x);
            fma2(d0, sa2, bv.x);
            fma2(d0, S2[2 * q], wv.x);
            S2[2 * q] = d0;
            ull d1 = mul2(vi2, kv.y);
            fma2(d1, sa2, bv.y);
            fma2(d1, S2[2 * q + 1], wv.y);
            S2[2 * q + 1] = d1;
        }

        // y partials
        ull ya = 0ull, yb = 0ull;
#pragma unroll
        for (int q = 0; q < 4; q++) {
            ulonglong2 rv = rp[q];
            fma2(ya, S2[2 * q], rv.x);
            fma2(yb, S2[2 * q + 1], rv.y);
        }

        // sa partials for t+1 (a(t+1) staged and waited)
        const ulonglong2* ap = (const ulonglong2*)(sn + 4 * 64 + jb);
        ull za = 0ull, zb = 0ull;
#pragma unroll
        for (int q = 0; q < 4; q++) {
            ulonglong2 av = ap[q];
            fma2(za, S2[2 * q], av.x);
            fma2(zb, S2[2 * q + 1], av.y);
        }

        float yv = (lo2(ya) + hi2(ya)) + (lo2(yb) + hi2(yb));
        float sv = (lo2(za) + hi2(za)) + (lo2(zb) + hi2(zb));
        yv += __shfl_xor_sync(0xffffffffu, yv, 1);
        sv += __shfl_xor_sync(0xffffffffu, sv, 1);
        yv += __shfl_xor_sync(0xffffffffu, yv, 2);
        sv += __shfl_xor_sync(0xffffffffu, sv, 2);
        sa = sv;
        if (jc == 0)
            y[base + (ll)t * Cc + i] = yv;
    }
}

// ---------------- E2 (writes YG planes) ----------------
__global__ __launch_bounds__(768) void e2_k(
    const float* __restrict__ y,
    const float* __restrict__ rr, const float* __restrict__ kk, const float* __restrict__ vv,
    const float* __restrict__ gg, const float* __restrict__ faaaa,
    const float* __restrict__ lnw, unsigned* __restrict__ ygp)
{
    int bt = blockIdx.x;
    int b = bt >> 11, t = bt & 2047;
    ll base = (ll)bt * Cc;
    int c = threadIdx.x;
    int w = c >> 5, h = c >> 6, j = c & 63, lane = c & 31;
    float yv = y[base + c];
    float rv = rr[base + c], kv = kk[base + c], vV = vv[base + c];
    float s1 = yv * yv;
    float s2 = rv * kv * faaaa[h * 64 + j];
#pragma unroll
    for (int o = 16; o; o >>= 1) {
        s1 += __shfl_xor_sync(0xffffffffu, s1, o);
        s2 += __shfl_xor_sync(0xffffffffu, s2, o);
    }
    __shared__ float sh1[24], sh2[24];
    if (lane == 0) { sh1[w] = s1; sh2[w] = s2; }
    __syncthreads();
    float tot = 0.f;
#pragma unroll
    for (int q = 0; q < 24; q++) tot += sh1[q];
    float scale = rsqrtf(tot * (1.f / 768.f) + 1e-5f);
    float rk = sh2[h * 2] + sh2[h * 2 + 1];
    float yo = (yv * scale * lnw[c] + rk * vV) * gg[base + c];
    ygp[(ll)b * 1572864 + (ll)(c >> 1) * 4096 + 2 * t + (c & 1)] = pack_hl(yo);
}

// ---------------- launch ----------------
#define SMEM64 (3 * (2 * 64 * 80 + 16 * 544))

extern "C" void kernel_launch(void* const* d_in, const int* in_sizes, int n_in,
                              void* d_out, int out_size)
{
    (void)in_sizes; (void)n_in; (void)out_size;
    const float* x       = (const float*)d_in[0];
    const float* tmaa_r  = (const float*)d_in[2];
    const float* tmaa_w  = (const float*)d_in[3];
    const float* tmaa_k  = (const float*)d_in[4];
    const float* tmaa_v  = (const float*)d_in[5];
    const float* tmaa_a  = (const float*)d_in[6];
    const float* tmaa_g  = (const float*)d_in[7];
    const float* tdecay  = (const float*)d_in[8];
    const float* faaaa   = (const float*)d_in[9];
    const float* taaaaa  = (const float*)d_in[10];
    const float* maa_w1  = (const float*)d_in[11];
    const float* maa_w2  = (const float*)d_in[12];
    const float* dec_w1  = (const float*)d_in[13];
    const float* dec_w2  = (const float*)d_in[14];
    const float* aaa_w1  = (const float*)d_in[15];
    const float* aaa_w2  = (const float*)d_in[16];
    const float* kkk_w1  = (const float*)d_in[17];
    const float* kkk_w2  = (const float*)d_in[18];
    const float* gate_w1 = (const float*)d_in[19];
    const float* gate_w2 = (const float*)d_in[20];
    const float* w_key   = (const float*)d_in[21];
    const float* w_val   = (const float*)d_in[22];
    const float* w_rec   = (const float*)d_in[23];
    const float* w_out   = (const float*)d_in[24];
    const float* lnw     = (const float*)d_in[25];
    float* out = (float*)d_out;

    static int attr_done = 0;
    if (!attr_done) {
        cudaFuncSetAttribute(gemm_k, cudaFuncAttributeMaxDynamicSharedMemorySize, SMEM64);
        attr_done = 1;
    }

    float* ws = 0;
    cudaGetSymbolAddress((void**)&ws, g_ws);

    unsigned* XP   = (unsigned*)(ws + WS_XP);
    unsigned* TMP  = (unsigned*)(ws + WS_TMP);
    unsigned* XBP  = (unsigned*)(ws + WS_XBP);
    float* RIN = ws + WS_RIN;
    float* Y   = ws + WS_Y;
    __nv_bfloat16* WPL = (__nv_bfloat16*)(ws + WS_WPL);

    // ---- weight prep ----
    {
        PrepTab pt;
        int i = 0;
        auto seg = [&](const float* s, int d, int M, int K, int sm, int sk) {
            pt.src[i] = s; pt.dst[i] = d; pt.M[i] = M; pt.K[i] = K; pt.sm[i] = sm; pt.sk[i] = sk; i++;
        };
        seg(maa_w1, 0, 384, 768, 768, 1);
        for (int n = 0; n < 6; n++) seg(maa_w2 + n * 49152, 294912 + n * 49152, 768, 64, 1, 768);
        seg(w_rec, 589824, 768, 384, 384, 1);
        seg(w_key, 884736, 768, 384, 384, 1);
        seg(w_val, 1179648, 768, 384, 384, 1);
        seg(dec_w1, 1474560, 64, 768, 768, 1);
        seg(kkk_w1, 1523712, 64, 768, 768, 1);
        seg(aaa_w1, 1572864, 64, 768, 768, 1);
        seg(dec_w2, 1622016, 768, 64, 64, 1);
        seg(kkk_w2, 1671168, 768, 64, 64, 1);
        seg(aaa_w2, 1720320, 768, 64, 64, 1);
        seg(gate_w1, 1769472, 192, 768, 768, 1);
        seg(gate_w2, 1916928, 768, 192, 192, 1);
        seg(w_out, 2064384, 768, 384, 384, 1);
        prep_w<<<dim3(1152, 1, 19), 256>>>(WPL, pt);
    }
    prep_x<<<(Bb * Cc * Tt) / 256, 256>>>(x, XP);

    // G1) TM planes = tanh(maa_w1 @ x): M=384, K=768
    {
        ZMap zm = {};
        for (int b = 0; b < 2; b++) {
            zm.b[b] = (ll)b * 1572864;
            zm.o[b] = (ll)b * 786432;
            zm.epi[b] = EPI_TANH;
            zm.Kz[b] = 768; zm.ym[b] = 6;
        }
        gemm_k<<<dim3(32, 6, 2), 256, SMEM64>>>(WPL, WTOT, XP, 0, TMP,
                                                0, 0, 2048, 1, 0, 0, zm);
    }

    // G2) MIX -> XB planes: z=n*2+b, M=768, K=64
    {
        ZMap zm = {};
        const float* tmaas[6] = {tmaa_r, tmaa_w, tmaa_k, tmaa_v, tmaa_a, tmaa_g};
        for (int n = 0; n < 6; n++)
            for (int b = 0; b < 2; b++) {
                int z = n * 2 + b;
                zm.a[z]  = 294912 + (ll)n * 49152;
                zm.b[z]  = (ll)b * 786432 + (ll)n * 131072;
                zm.o[z]  = ((ll)n * 2 + b) * 1572864;
                zm.x1[z] = (ll)(tmaas[n] - tmaa_r);
                zm.x2[z] = (ll)b * CTll;
                zm.epi[z] = EPI_MIX;
                zm.Kz[z] = 64; zm.ym[z] = 12;
            }
        gemm_k<<<dim3(32, 12, 12), 256, SMEM64>>>(WPL, WTOT, TMP, 0, XBP,
                                                  0, 0, 2048, 1, tmaa_r, x, zm);
    }

    // G3) convs (r,k,v) -> RIN fp32: z=q*4+g*2+b, M=384, K=384 (transposed store)
    {
        ZMap zm = {};
        const int xbi[3] = {0, 2, 3};
        const int rio[3] = {0, 2, 3};
        for (int q = 0; q < 3; q++)
            for (int g = 0; g < 2; g++)
                for (int b = 0; b < 2; b++) {
                    int z = q * 4 + g * 2 + b;
                    zm.a[z] = 589824 + (ll)q * 294912 + (ll)g * 147456;
                    zm.b[z] = ((ll)xbi[q] * 2 + b) * 1572864 + (ll)g * 786432;
                    zm.o[z] = (ll)rio[q] * BTCll + (ll)b * CTll + g * 384;
                    zm.epi[z] = EPI_NONE;
                    zm.Kz[z] = 384; zm.ym[z] = 6;
                }
        gemm_k<<<dim3(32, 6, 12), 256, SMEM64>>>(WPL, WTOT, XBP, RIN, 0,
                                                 1, Cc, 2048, 0, 0, 0, zm);
    }

    // G45) lora stage1 (dec,kkk,aaa) + gate stage1, merged: K=768
    {
        ZMap zm = {};
        const int sl[3] = {1, 2, 4};
        for (int q = 0; q < 3; q++)
            for (int b = 0; b < 2; b++) {
                int z = q * 2 + b;
                zm.a[z] = 1474560 + (ll)q * 49152;
                zm.b[z] = ((ll)sl[q] * 2 + b) * 1572864;
                zm.o[z] = WS_H1P + ((ll)q * 2 + b) * 131072;
                zm.epi[z] = EPI_TANH;
                zm.Kz[z] = 768; zm.ym[z] = 1;
            }
        for (int b = 0; b < 2; b++) {
            int z = 6 + b;
            zm.a[z] = 1769472;
            zm.b[z] = (10LL + b) * 1572864;
            zm.o[z] = WS_TM2P + (ll)b * 393216;
            zm.epi[z] = EPI_TANH;
            zm.Kz[z] = 768; zm.ym[z] = 3;
        }
        gemm_k<<<dim3(32, 3, 8), 256, SMEM64>>>(WPL, WTOT, XBP, 0, (unsigned*)ws,
                                                0, 0, 2048, 1, 0, 0, zm);
    }

    // G67) lora stage2 (wdec, KL, AS) + gate stage2, merged (transposed store)
    {
        ZMap zm = {};
        ll od[3] = {WS_RIN + BTCll, WS_KL, WS_AS};
        const int ep[3] = {EPI_DECAY, EPI_NONE, EPI_SIG};
        ll xd[3] = {0, 0, (ll)(taaaaa - tdecay)};
        for (int q = 0; q < 3; q++)
            for (int b = 0; b < 2; b++) {
                int z = q * 2 + b;
                zm.a[z]  = 1622016 + (ll)q * 49152;
                zm.b[z]  = WS_H1P + ((ll)q * 2 + b) * 131072;
                zm.o[z]  = od[q] + (ll)b * CTll;
                zm.x1[z] = xd[q];
                zm.epi[z] = ep[q];
                zm.Kz[z] = 64; zm.ym[z] = 12;
            }
        for (int b = 0; b < 2; b++) {
            int z = 6 + b;
            zm.a[z] = 1916928;
            zm.b[z] = WS_TM2P + (ll)b * 393216;
            zm.o[z] = WS_GT + (ll)b * CTll;
            zm.epi[z] = EPI_NONE;
            zm.Kz[z] = 192; zm.ym[z] = 12;
        }
        gemm_k<<<dim3(32, 12, 8), 256, SMEM64>>>(WPL, WTOT, (unsigned*)ws, ws, 0,
                                                 1, Cc, 2048, 0, tdecay, 0, zm);
    }

    // E1
    e1_k<<<(Bb * Tt * Hh) / 8, 256>>>(RIN + 2 * BTCll, ws + WS_KL, ws + WS_AS,
                                      RIN + 4 * BTCll, RIN + 5 * BTCll);

    // WKV7
    wkv7_k<<<Bb * Hh * RS, 64>>>(RIN, Y);

    // E2 -> YG planes (reuse XP)
    e2_k<<<Bb * Tt, 768>>>(Y, RIN, RIN + 2 * BTCll, RIN + 3 * BTCll,
                           ws + WS_GT, faaaa, lnw, XP);

    // G11) output conv: z=g*2+b, M=384, K=384, out fp32 (B,C,T)
    {
        ZMap zm = {};
        for (int g = 0; g < 2; g++)
            for (int b = 0; b < 2; b++) {
                int z = g * 2 + b;
                zm.a[z] = 2064384 + (ll)g * 147456;
                zm.b[z] = (ll)b * 1572864 + (ll)g * 786432;
                zm.o[z] = (ll)b * CTll + (ll)g * 384 * Tt;
                zm.epi[z] = EPI_NONE;
                zm.Kz[z] = 384; zm.ym[z] = 6;
            }
        gemm_k<<<dim3(32, 6, 4), 256, SMEM64>>>(WPL, WTOT, XP, out, 0,
                                                Tt, 1, 2048, 0, 0, 0, zm);
    }
}

// round 16
// speedup vs baseline: 2.1012x; 1.0776x over previous
#include <cuda_runtime.h>
#include <cuda_bf16.h>
#include <math.h>

#define Bb 2
#define Tt 2048
#define Cc 768
#define Hh 12

typedef unsigned long long ull;
typedef long long ll;

static const ll CTll  = (ll)Cc * Tt;
static const ll BTCll = (ll)Bb * Tt * Cc;

// ---------------- workspace ----------------
#define WS_XP   0LL
#define WS_TMP  3145728LL
#define WS_XBP  4718592LL
#define WS_H1P  23592960LL
#define WS_TM2P 24379392LL
#define WS_GT   25165824LL
#define WS_RIN  28311552LL   // 6 x (B,T,C) fp32: r,w,k,v,am,bm
#define WS_KL   47185920LL
#define WS_AS   50331648LL
#define WS_Y    53477376LL
#define WS_WPL  56623104LL   // weight bf16 planes
__device__ float g_ws[59080704];

#define WTOT 2359296

// ---------------- helpers ----------------
__device__ __forceinline__ void fma2(ull &d, ull a, ull b) {
    asm("fma.rn.f32x2 %0, %1, %2, %0;" : "+l"(d) : "l"(a), "l"(b));
}
__device__ __forceinline__ ull mul2(ull a, ull b) {
    ull d; asm("mul.rn.f32x2 %0, %1, %2;" : "=l"(d) : "l"(a), "l"(b)); return d;
}
__device__ __forceinline__ ull pk2(float v) {
    ull r; unsigned u = __float_as_uint(v);
    asm("mov.b64 %0, {%1, %1};" : "=l"(r) : "r"(u));
    return r;
}
__device__ __forceinline__ float lo2(ull p) { return __uint_as_float((unsigned)p); }
__device__ __forceinline__ float hi2(ull p) { return __uint_as_float((unsigned)(p >> 32)); }

__device__ __forceinline__ unsigned pack_hl(float v) {
    __nv_bfloat16 h = __float2bfloat16(v);
    float hf = __bfloat162float(h);
    __nv_bfloat16 l = __float2bfloat16(v - hf);
    return (unsigned)__bfloat16_as_ushort(h) | ((unsigned)__bfloat16_as_ushort(l) << 16);
}
__device__ __forceinline__ unsigned prmt(unsigned a, unsigned b, unsigned s) {
    unsigned d; asm("prmt.b32 %0,%1,%2,%3;" : "=r"(d) : "r"(a), "r"(b), "r"(s)); return d;
}
__device__ __forceinline__ void ldsm4(unsigned &r0, unsigned &r1, unsigned &r2, unsigned &r3,
                                      unsigned saddr) {
    asm volatile("ldmatrix.sync.aligned.m8n8.x4.shared.b16 {%0,%1,%2,%3}, [%4];"
        : "=r"(r0), "=r"(r1), "=r"(r2), "=r"(r3) : "r"(saddr));
}
__device__ __forceinline__ void mma16(float c[4], unsigned a0, unsigned a1, unsigned a2,
                                      unsigned a3, unsigned b0, unsigned b1) {
    asm volatile("mma.sync.aligned.m16n8k16.row.col.f32.bf16.bf16.f32 "
        "{%0,%1,%2,%3}, {%4,%5,%6,%7}, {%8,%9}, {%0,%1,%2,%3};"
        : "+f"(c[0]), "+f"(c[1]), "+f"(c[2]), "+f"(c[3])
        : "r"(a0), "r"(a1), "r"(a2), "r"(a3), "r"(b0), "r"(b1));
}
__device__ __forceinline__ void cpa16(void* dst, const void* src) {
    unsigned d = (unsigned)__cvta_generic_to_shared(dst);
    asm volatile("cp.async.cg.shared.global [%0], [%1], 16;" :: "r"(d), "l"(src));
}
__device__ __forceinline__ void cpa4(void* dst, const void* src) {
    unsigned d = (unsigned)__cvta_generic_to_shared(dst);
    asm volatile("cp.async.ca.shared.global [%0], [%1], 4;" :: "r"(d), "l"(src));
}
#define CP_COMMIT asm volatile("cp.async.commit_group;")
#define CP_WAIT0  asm volatile("cp.async.wait_group 0;")
#define CP_WAIT2  asm volatile("cp.async.wait_group 2;")
#define CP_WAIT3  asm volatile("cp.async.wait_group 3;")

// ---------------- prep kernels ----------------
struct PrepTab {
    const float* src[19];
    int dst[19], M[19], K[19], sm[19], sk[19];
};

__global__ __launch_bounds__(256) void prep_w(__nv_bfloat16* hi, PrepTab pt) {
    int sgi = blockIdx.z;
    int idx = blockIdx.x * 256 + threadIdx.x;
    int MK = pt.M[sgi] * pt.K[sgi];
    if (idx >= MK) return;
    int k = idx % pt.K[sgi];
    int m = idx / pt.K[sgi];
    float v = pt.src[sgi][(ll)m * pt.sm[sgi] + (ll)k * pt.sk[sgi]];
    __nv_bfloat16 h = __float2bfloat16(v);
    float hf = __bfloat162float(h);
    __nv_bfloat16 l = __float2bfloat16(v - hf);
    hi[pt.dst[sgi] + idx] = h;
    hi[WTOT + pt.dst[sgi] + idx] = l;
}

__global__ __launch_bounds__(256) void prep_x(const float* __restrict__ x,
                                              unsigned* __restrict__ xp) {
    int idx = blockIdx.x * 256 + threadIdx.x;
    int t = idx & 2047;
    int rest = idx >> 11;
    int c = rest % Cc, b = rest / Cc;
    xp[(ll)b * 1572864 + (ll)(c >> 1) * 4096 + 2 * t + (c & 1)] = pack_hl(x[idx]);
}

// ---------------- GEMM ----------------
enum { EPI_NONE = 0, EPI_TANH = 1, EPI_MIX = 2, EPI_DECAY = 3, EPI_SIG = 4 };

struct ZMap {
    ll a[12], b[12], o[12], x1[12], x2[12];
    int epi[12], Kz[12], ym[12];
};

__device__ __forceinline__ float apply_epi(float v, int epi, const float* p1,
                                           const float* x2, int m, int n, int N) {
    if (epi == EPI_TANH) {
        v = tanhf(v);
    } else if (epi == EPI_MIX) {
        v = x2[(ll)m * N + n] * (1.f + p1[m] + v);
    } else if (epi == EPI_DECAY) {
        float u = -(p1[m] + v);
        float sp = fmaxf(u, 0.f) + log1pf(expf(-fabsf(u)));
        v = expf(-expf(-sp - 0.5f));
    } else if (epi == EPI_SIG) {
        v = 1.f / (1.f + expf(-(p1[m] + v)));
    }
    return v;
}

// block tile 64 x 64, KC=32, 4-stage ring, 256 threads (8 warps: 2m x 4n), 3 CTAs/SM
__global__ __launch_bounds__(256, 3) void gemm_k(
    const __nv_bfloat16* __restrict__ Apl, ll Atot,
    const unsigned* __restrict__ Bpl,
    float* __restrict__ Ob, unsigned* __restrict__ Pb,
    int sOM, int sON, int N, int omode,
    const float* __restrict__ aux1, const float* __restrict__ aux2,
    ZMap zm)
{
    constexpr int MT = 2;
    constexpr int ABYTES = 64 * 80;
    constexpr int STG = 2 * ABYTES + 16 * 544;
    extern __shared__ char smem[];

    const int z = blockIdx.z;
    if ((int)blockIdx.y >= zm.ym[z]) return;
    const int K = zm.Kz[z];
    const __nv_bfloat16* Ahi = Apl + zm.a[z];
    const unsigned* Bg = Bpl + zm.b[z];
    const ll zo = zm.o[z];
    const float* p1 = aux1 ? aux1 + zm.x1[z] : (const float*)0;
    const float* x2 = aux2 ? aux2 + zm.x2[z] : (const float*)0;
    const int epi = zm.epi[z];

    const int tid = threadIdx.x;
    const int m0 = blockIdx.y * 64, n0 = blockIdx.x * 64;
    const int warp = tid >> 5, lane = tid & 31;
    const int qr = lane >> 2, qc = lane & 3;
    const int wm0 = (warp & 1) * 32;
    const int wn0 = (warp >> 1) * 16;
    const int rowW = 2 * N;

    unsigned sbase = (unsigned)__cvta_generic_to_shared(smem);

    auto issue = [&](int kt) {
        char* S = smem + (kt & 3) * STG;
        int k0 = kt * 32;
        {
            int am = tid >> 2, ae = (tid & 3) * 8;
            const __nv_bfloat16* s0 = Ahi + (ll)(m0 + am) * K + k0 + ae;
            char* d0 = S + am * 80 + ae * 2;
            cpa16(d0, s0);
            cpa16(d0 + ABYTES, s0 + Atot);
        }
        {
            int kp = tid >> 4, wo = (tid & 15) * 8;
            const unsigned* s = Bg + (ll)(k0 / 2 + kp) * rowW + n0 * 2 + wo;
            char* d = S + 2 * ABYTES + kp * 544 + wo * 4;
            cpa16(d, s); cpa16(d + 16, s + 4);
        }
    };

    float c[MT][2][4];
#pragma unroll
    for (int mt = 0; mt < MT; mt++)
#pragma unroll
        for (int nt = 0; nt < 2; nt++)
#pragma unroll
            for (int r = 0; r < 4; r++) c[mt][nt][r] = 0.f;

    const int nk = K >> 5;
    issue(0); CP_COMMIT;
    if (nk > 1) issue(1);
    CP_COMMIT;
    if (nk > 2) issue(2);
    CP_COMMIT;

    for (int kt = 0; kt < nk; kt++) {
        CP_WAIT2;
        __syncthreads();
        if (kt + 3 < nk) issue(kt + 3);
        CP_COMMIT;

        char* Sst = smem + (kt & 3) * STG;
        unsigned SAu = sbase + (kt & 3) * STG;
        char* Sb = Sst + 2 * ABYTES;

#pragma unroll
        for (int s = 0; s < 2; s++) {
            unsigned bh[2][2], bl[2][2];
#pragma unroll
            for (int nt = 0; nt < 2; nt++) {
                int n = wn0 + nt * 8 + qr;
                uint2 w01 = *(const uint2*)(Sb + (s * 8 + qc) * 544 + n * 8);
                uint2 w23 = *(const uint2*)(Sb + (s * 8 + qc + 4) * 544 + n * 8);
                bh[nt][0] = prmt(w01.x, w01.y, 0x5410); bl[nt][0] = prmt(w01.x, w01.y, 0x7632);
                bh[nt][1] = prmt(w23.x, w23.y, 0x5410); bl[nt][1] = prmt(w23.x, w23.y, 0x7632);
            }
#pragma unroll
            for (int mt = 0; mt < MT; mt++) {
                unsigned aaddr = SAu + (wm0 + mt * 16 + (lane & 15)) * 80 + (lane >> 4) * 16 + s * 32;
                unsigned h0, h1, h2, h3, l0, l1, l2, l3;
                ldsm4(h0, h1, h2, h3, aaddr);
                ldsm4(l0, l1, l2, l3, aaddr + ABYTES);
#pragma unroll
                for (int nt = 0; nt < 2; nt++) {
                    mma16(c[mt][nt], h0, h1, h2, h3, bh[nt][0], bh[nt][1]);
                    mma16(c[mt][nt], l0, l1, l2, l3, bh[nt][0], bh[nt][1]);
                    mma16(c[mt][nt], h0, h1, h2, h3, bl[nt][0], bl[nt][1]);
                }
            }
        }
    }

    const bool use_tr = (omode == 0) && (sON != 1);
    if (use_tr) __syncthreads();
    float* Tf = (float*)smem;

#pragma unroll
    for (int mt = 0; mt < MT; mt++) {
#pragma unroll
        for (int nt = 0; nt < 2; nt++) {
            int mL = wm0 + mt * 16 + qr;
            int nL = wn0 + nt * 8 + qc * 2;
            int mA = m0 + mL;
            int nA = n0 + nL;
            float v0 = apply_epi(c[mt][nt][0], epi, p1, x2, mA, nA, N);
            float v1 = apply_epi(c[mt][nt][1], epi, p1, x2, mA, nA + 1, N);
            float v2 = apply_epi(c[mt][nt][2], epi, p1, x2, mA + 8, nA, N);
            float v3 = apply_epi(c[mt][nt][3], epi, p1, x2, mA + 8, nA + 1, N);
            if (omode == 0) {
                if (sON == 1) {
                    float* O = Ob + zo;
                    *(float2*)(O + (ll)mA * sOM + nA)       = make_float2(v0, v1);
                    *(float2*)(O + (ll)(mA + 8) * sOM + nA) = make_float2(v2, v3);
                } else {
                    Tf[nL * 68 + mL]           = v0;
                    Tf[(nL + 1) * 68 + mL]     = v1;
                    Tf[nL * 68 + mL + 8]       = v2;
                    Tf[(nL + 1) * 68 + mL + 8] = v3;
                }
            } else {
                unsigned* P = Pb + zo;
                ll r0 = (ll)(mA >> 1) * rowW + (mA & 1);
                ll r1 = r0 + (ll)4 * rowW;
                P[r0 + 2 * nA]       = pack_hl(v0);
                P[r0 + 2 * (nA + 1)] = pack_hl(v1);
                P[r1 + 2 * nA]       = pack_hl(v2);
                P[r1 + 2 * (nA + 1)] = pack_hl(v3);
            }
        }
    }

    if (use_tr) {
        __syncthreads();
        float* O = Ob + zo;
#pragma unroll
        for (int p = 0; p < 4; p++) {
            int row = p * 16 + (tid >> 4);
            int c4 = (tid & 15) * 4;
            float4 v = *(float4*)&Tf[row * 68 + c4];
            *(float4*)(O + (ll)(n0 + row) * sON + m0 + c4) = v;
        }
    }
}

// ---------------- E1 ----------------
__global__ __launch_bounds__(256) void e1_k(
    const float* __restrict__ kc, const float* __restrict__ kl,
    const float* __restrict__ asig, float* __restrict__ am, float* __restrict__ bm)
{
    int gw = (int)((blockIdx.x * blockDim.x + threadIdx.x) >> 5);
    int lane = threadIdx.x & 31;
    ll base = (ll)gw * 64;
    float k1 = kc[base + lane]      + kl[base + lane];
    float k2 = kc[base + lane + 32] + kl[base + lane + 32];
    float ss = k1 * k1 + k2 * k2;
#pragma unroll
    for (int o = 16; o; o >>= 1) ss += __shfl_xor_sync(0xffffffffu, ss, o);
    float inv = 1.f / fmaxf(sqrtf(ss), 1e-12f);
    float n1 = k1 * inv, n2 = k2 * inv;
    am[base + lane]      = -n1;
    am[base + lane + 32] = -n2;
    bm[base + lane]      = n1 * asig[base + lane];
    bm[base + lane + 32] = n2 * asig[base + lane + 32];
}

// ---------------- WKV7: RS=4, cp.async 8-buffer ring (5 steps ahead) ----------------
#define RS 4
__global__ __launch_bounds__(64) void wkv7_k(const float* __restrict__ rin, float* __restrict__ y)
{
    int blk = blockIdx.x;
    int rs = blk & 3;
    int bh = blk >> 2;
    int b = bh / Hh, h = bh % Hh;
    ll base = (ll)b * Tt * Cc + (ll)h * 64;

    int tid = threadIdx.x;
    int lr = tid >> 2, jc = tid & 3;
    int i = rs * 16 + lr;
    int jb = jc << 4;

    __shared__ __align__(16) float sh[8][384];

    auto stage = [&](int tt) {
        float* sd = sh[tt & 7];
        ll off = base + (ll)tt * Cc;
#pragma unroll
        for (int q = 0; q < 6; q++)
            cpa4(&sd[q * 64 + tid], &rin[(ll)q * BTCll + off + tid]);
        CP_COMMIT;
    };

    stage(0);
    stage(1);
    stage(2);
    stage(3);
    stage(4);

    ull S2[8];
#pragma unroll
    for (int u = 0; u < 8; u++) S2[u] = 0ull;
    float sa = 0.f;

    for (int t = 0; t < Tt; t++) {
        // committed = 5+t; wait_group 3 -> groups <= t+1 complete (sb and sn ready)
        if (t + 5 < Tt) { CP_WAIT3; } else { CP_WAIT0; }
        __syncthreads();               // fences step t-1 reads before buffer (t-3)&7 reuse
        if (t + 5 < Tt) stage(t + 5);

        const float* sb = sh[t & 7];
        const float* sn = sh[(t + 1) & 7];
        float vi = sb[3 * 64 + i];
        ull vi2 = pk2(vi), sa2 = pk2(sa);

        const ulonglong2* wp = (const ulonglong2*)(sb + 1 * 64 + jb);
        const ulonglong2* kp = (const ulonglong2*)(sb + 2 * 64 + jb);
        const ulonglong2* bp = (const ulonglong2*)(sb + 5 * 64 + jb);
        const ulonglong2* rp = (const ulonglong2*)(sb + 0 * 64 + jb);

        // S = S*w + sa*b + vi*k
#pragma unroll
        for (int q = 0; q < 4; q++) {
            ulonglong2 wv = wp[q], kv = kp[q], bv = bp[q];
            ull d0 = mul2(vi2, kv.x);
            fma2(d0, sa2, bv.x);
            fma2(d0, S2[2 * q], wv.x);
            S2[2 * q] = d0;
            ull d1 = mul2(vi2, kv.y);
            fma2(d1, sa2, bv.y);
            fma2(d1, S2[2 * q + 1], wv.y);
            S2[2 * q + 1] = d1;
        }

        // y partials
        ull ya = 0ull, yb = 0ull;
#pragma unroll
        for (int q = 0; q < 4; q++) {
            ulonglong2 rv = rp[q];
            fma2(ya, S2[2 * q], rv.x);
            fma2(yb, S2[2 * q + 1], rv.y);
        }

        // sa partials for t+1
        const ulonglong2* ap = (const ulonglong2*)(sn + 4 * 64 + jb);
        ull za = 0ull, zb = 0ull;
#pragma unroll
        for (int q = 0; q < 4; q++) {
            ulonglong2 av = ap[q];
            fma2(za, S2[2 * q], av.x);
            fma2(zb, S2[2 * q + 1], av.y);
        }

        float yv = (lo2(ya) + hi2(ya)) + (lo2(yb) + hi2(yb));
        float sv = (lo2(za) + hi2(za)) + (lo2(zb) + hi2(zb));
        yv += __shfl_xor_sync(0xffffffffu, yv, 1);
        sv += __shfl_xor_sync(0xffffffffu, sv, 1);
        yv += __shfl_xor_sync(0xffffffffu, yv, 2);
        sv += __shfl_xor_sync(0xffffffffu, sv, 2);
        sa = sv;
        if (jc == 0)
            y[base + (ll)t * Cc + i] = yv;
    }
}

// ---------------- E2 (writes YG planes) ----------------
__global__ __launch_bounds__(768) void e2_k(
    const float* __restrict__ y,
    const float* __restrict__ rr, const float* __restrict__ kk, const float* __restrict__ vv,
    const float* __restrict__ gg, const float* __restrict__ faaaa,
    const float* __restrict__ lnw, unsigned* __restrict__ ygp)
{
    int bt = blockIdx.x;
    int b = bt >> 11, t = bt & 2047;
    ll base = (ll)bt * Cc;
    int c = threadIdx.x;
    int w = c >> 5, h = c >> 6, j = c & 63, lane = c & 31;
    float yv = y[base + c];
    float rv = rr[base + c], kv = kk[base + c], vV = vv[base + c];
    float s1 = yv * yv;
    float s2 = rv * kv * faaaa[h * 64 + j];
#pragma unroll
    for (int o = 16; o; o >>= 1) {
        s1 += __shfl_xor_sync(0xffffffffu, s1, o);
        s2 += __shfl_xor_sync(0xffffffffu, s2, o);
    }
    __shared__ float sh1[24], sh2[24];
    if (lane == 0) { sh1[w] = s1; sh2[w] = s2; }
    __syncthreads();
    float tot = 0.f;
#pragma unroll
    for (int q = 0; q < 24; q++) tot += sh1[q];
    float scale = rsqrtf(tot * (1.f / 768.f) + 1e-5f);
    float rk = sh2[h * 2] + sh2[h * 2 + 1];
    float yo = (yv * scale * lnw[c] + rk * vV) * gg[base + c];
    ygp[(ll)b * 1572864 + (ll)(c >> 1) * 4096 + 2 * t + (c & 1)] = pack_hl(yo);
}

// ---------------- launch ----------------
#define SMEM64 (4 * (2 * 64 * 80 + 16 * 544))

extern "C" void kernel_launch(void* const* d_in, const int* in_sizes, int n_in,
                              void* d_out, int out_size)
{
    (void)in_sizes; (void)n_in; (void)out_size;
    const float* x       = (const float*)d_in[0];
    const float* tmaa_r  = (const float*)d_in[2];
    const float* tmaa_w  = (const float*)d_in[3];
    const float* tmaa_k  = (const float*)d_in[4];
    const float* tmaa_v  = (const float*)d_in[5];
    const float* tmaa_a  = (const float*)d_in[6];
    const float* tmaa_g  = (const float*)d_in[7];
    const float* tdecay  = (const float*)d_in[8];
    const float* faaaa   = (const float*)d_in[9];
    const float* taaaaa  = (const float*)d_in[10];
    const float* maa_w1  = (const float*)d_in[11];
    const float* maa_w2  = (const float*)d_in[12];
    const float* dec_w1  = (const float*)d_in[13];
    const float* dec_w2  = (const float*)d_in[14];
    const float* aaa_w1  = (const float*)d_in[15];
    const float* aaa_w2  = (const float*)d_in[16];
    const float* kkk_w1  = (const float*)d_in[17];
    const float* kkk_w2  = (const float*)d_in[18];
    const float* gate_w1 = (const float*)d_in[19];
    const float* gate_w2 = (const float*)d_in[20];
    const float* w_key   = (const float*)d_in[21];
    const float* w_val   = (const float*)d_in[22];
    const float* w_rec   = (const float*)d_in[23];
    const float* w_out   = (const float*)d_in[24];
    const float* lnw     = (const float*)d_in[25];
    float* out = (float*)d_out;

    static int attr_done = 0;
    if (!attr_done) {
        cudaFuncSetAttribute(gemm_k, cudaFuncAttributeMaxDynamicSharedMemorySize, SMEM64);
        attr_done = 1;
    }

    float* ws = 0;
    cudaGetSymbolAddress((void**)&ws, g_ws);

    unsigned* XP   = (unsigned*)(ws + WS_XP);
    unsigned* TMP  = (unsigned*)(ws + WS_TMP);
    unsigned* XBP  = (unsigned*)(ws + WS_XBP);
    float* RIN = ws + WS_RIN;
    float* Y   = ws + WS_Y;
    __nv_bfloat16* WPL = (__nv_bfloat16*)(ws + WS_WPL);

    // ---- weight prep ----
    {
        PrepTab pt;
        int i = 0;
        auto seg = [&](const float* s, int d, int M, int K, int sm, int sk) {
            pt.src[i] = s; pt.dst[i] = d; pt.M[i] = M; pt.K[i] = K; pt.sm[i] = sm; pt.sk[i] = sk; i++;
        };
        seg(maa_w1, 0, 384, 768, 768, 1);
        for (int n = 0; n < 6; n++) seg(maa_w2 + n * 49152, 294912 + n * 49152, 768, 64, 1, 768);
        seg(w_rec, 589824, 768, 384, 384, 1);
        seg(w_key, 884736, 768, 384, 384, 1);
        seg(w_val, 1179648, 768, 384, 384, 1);
        seg(dec_w1, 1474560, 64, 768, 768, 1);
        seg(kkk_w1, 1523712, 64, 768, 768, 1);
        seg(aaa_w1, 1572864, 64, 768, 768, 1);
        seg(dec_w2, 1622016, 768, 64, 64, 1);
        seg(kkk_w2, 1671168, 768, 64, 64, 1);
        seg(aaa_w2, 1720320, 768, 64, 64, 1);
        seg(gate_w1, 1769472, 192, 768, 768, 1);
        seg(gate_w2, 1916928, 768, 192, 192, 1);
        seg(w_out, 2064384, 768, 384, 384, 1);
        prep_w<<<dim3(1152, 1, 19), 256>>>(WPL, pt);
    }
    prep_x<<<(Bb * Cc * Tt) / 256, 256>>>(x, XP);

    // G1) TM planes = tanh(maa_w1 @ x): M=384, K=768
    {
        ZMap zm = {};
        for (int b = 0; b < 2; b++) {
            zm.b[b] = (ll)b * 1572864;
            zm.o[b] = (ll)b * 786432;
            zm.epi[b] = EPI_TANH;
            zm.Kz[b] = 768; zm.ym[b] = 6;
        }
        gemm_k<<<dim3(32, 6, 2), 256, SMEM64>>>(WPL, WTOT, XP, 0, TMP,
                                                0, 0, 2048, 1, 0, 0, zm);
    }

    // G2) MIX -> XB planes: z=n*2+b, M=768, K=64
    {
        ZMap zm = {};
        const float* tmaas[6] = {tmaa_r, tmaa_w, tmaa_k, tmaa_v, tmaa_a, tmaa_g};
        for (int n = 0; n < 6; n++)
            for (int b = 0; b < 2; b++) {
                int z = n * 2 + b;
                zm.a[z]  = 294912 + (ll)n * 49152;
                zm.b[z]  = (ll)b * 786432 + (ll)n * 131072;
                zm.o[z]  = ((ll)n * 2 + b) * 1572864;
                zm.x1[z] = (ll)(tmaas[n] - tmaa_r);
                zm.x2[z] = (ll)b * CTll;
                zm.epi[z] = EPI_MIX;
                zm.Kz[z] = 64; zm.ym[z] = 12;
            }
        gemm_k<<<dim3(32, 12, 12), 256, SMEM64>>>(WPL, WTOT, TMP, 0, XBP,
                                                  0, 0, 2048, 1, tmaa_r, x, zm);
    }

    // G3) convs (r,k,v) -> RIN fp32: z=q*4+g*2+b, M=384, K=384 (transposed store)
    {
        ZMap zm = {};
        const int xbi[3] = {0, 2, 3};
        const int rio[3] = {0, 2, 3};
        for (int q = 0; q < 3; q++)
            for (int g = 0; g < 2; g++)
                for (int b = 0; b < 2; b++) {
                    int z = q * 4 + g * 2 + b;
                    zm.a[z] = 589824 + (ll)q * 294912 + (ll)g * 147456;
                    zm.b[z] = ((ll)xbi[q] * 2 + b) * 1572864 + (ll)g * 786432;
                    zm.o[z] = (ll)rio[q] * BTCll + (ll)b * CTll + g * 384;
                    zm.epi[z] = EPI_NONE;
                    zm.Kz[z] = 384; zm.ym[z] = 6;
                }
        gemm_k<<<dim3(32, 6, 12), 256, SMEM64>>>(WPL, WTOT, XBP, RIN, 0,
                                                 1, Cc, 2048, 0, 0, 0, zm);
    }

    // G45) lora stage1 (dec,kkk,aaa) + gate stage1, merged: K=768
    {
        ZMap zm = {};
        const int sl[3] = {1, 2, 4};
        for (int q = 0; q < 3; q++)
            for (int b = 0; b < 2; b++) {
                int z = q * 2 + b;
                zm.a[z] = 1474560 + (ll)q * 49152;
                zm.b[z] = ((ll)sl[q] * 2 + b) * 1572864;
                zm.o[z] = WS_H1P + ((ll)q * 2 + b) * 131072;
                zm.epi[z] = EPI_TANH;
                zm.Kz[z] = 768; zm.ym[z] = 1;
            }
        for (int b = 0; b < 2; b++) {
            int z = 6 + b;
            zm.a[z] = 1769472;
            zm.b[z] = (10LL + b) * 1572864;
            zm.o[z] = WS_TM2P + (ll)b * 393216;
            zm.epi[z] = EPI_TANH;
            zm.Kz[z] = 768; zm.ym[z] = 3;
        }
        gemm_k<<<dim3(32, 3, 8), 256, SMEM64>>>(WPL, WTOT, XBP, 0, (unsigned*)ws,
                                                0, 0, 2048, 1, 0, 0, zm);
    }

    // G67) lora stage2 (wdec, KL, AS) + gate stage2, merged (transposed store)
    {
        ZMap zm = {};
        ll od[3] = {WS_RIN + BTCll, WS_KL, WS_AS};
        const int ep[3] = {EPI_DECAY, EPI_NONE, EPI_SIG};
        ll xd[3] = {0, 0, (ll)(taaaaa - tdecay)};
        for (int q = 0; q < 3; q++)
            for (int b = 0; b < 2; b++) {
                int z = q * 2 + b;
                zm.a[z]  = 1622016 + (ll)q * 49152;
                zm.b[z]  = WS_H1P + ((ll)q * 2 + b) * 131072;
                zm.o[z]  = od[q] + (ll)b * CTll;
                zm.x1[z] = xd[q];
                zm.epi[z] = ep[q];
                zm.Kz[z] = 64; zm.ym[z] = 12;
            }
        for (int b = 0; b < 2; b++) {
            int z = 6 + b;
            zm.a[z] = 1916928;
            zm.b[z] = WS_TM2P + (ll)b * 393216;
            zm.o[z] = WS_GT + (ll)b * CTll;
            zm.epi[z] = EPI_NONE;
            zm.Kz[z] = 192; zm.ym[z] = 12;
        }
        gemm_k<<<dim3(32, 12, 8), 256, SMEM64>>>(WPL, WTOT, (unsigned*)ws, ws, 0,
                                                 1, Cc, 2048, 0, tdecay, 0, zm);
    }

    // E1
    e1_k<<<(Bb * Tt * Hh) / 8, 256>>>(RIN + 2 * BTCll, ws + WS_KL, ws + WS_AS,
                                      RIN + 4 * BTCll, RIN + 5 * BTCll);

    // WKV7
    wkv7_k<<<Bb * Hh * RS, 64>>>(RIN, Y);

    // E2 -> YG planes (reuse XP)
    e2_k<<<Bb * Tt, 768>>>(Y, RIN, RIN + 2 * BTCll, RIN + 3 * BTCll,
                           ws + WS_GT, faaaa, lnw, XP);

    // G11) output conv: z=g*2+b, M=384, K=384, out fp32 (B,C,T)
    {
        ZMap zm = {};
        for (int g = 0; g < 2; g++)
            for (int b = 0; b < 2; b++) {
                int z = g * 2 + b;
                zm.a[z] = 2064384 + (ll)g * 147456;
                zm.b[z] = (ll)b * 1572864 + (ll)g * 786432;
                zm.o[z] = (ll)b * CTll + (ll)g * 384 * Tt;
                zm.epi[z] = EPI_NONE;
                zm.Kz[z] = 384; zm.ym[z] = 6;
            }
        gemm_k<<<dim3(32, 6, 4), 256, SMEM64>>>(WPL, WTOT, XP, out, 0,
                                                Tt, 1, 2048, 0, 0, 0, zm);
    }
}

// round 17
// speedup vs baseline: 2.1054x; 1.0020x over previous
#include <cuda_runtime.h>
#include <cuda_bf16.h>
#include <math.h>

#define Bb 2
#define Tt 2048
#define Cc 768
#define Hh 12

typedef unsigned long long ull;
typedef long long ll;

static const ll CTll  = (ll)Cc * Tt;
static const ll BTCll = (ll)Bb * Tt * Cc;

// ---------------- workspace ----------------
#define WS_XP   0LL
#define WS_TMP  3145728LL
#define WS_XBP  4718592LL
#define WS_H1P  23592960LL
#define WS_TM2P 24379392LL
#define WS_GT   25165824LL
#define WS_RIN  28311552LL   // 6 x (B,T,C) fp32: r,w,k,v,am,bm
#define WS_KL   47185920LL
#define WS_AS   50331648LL
#define WS_Y    53477376LL
#define WS_WPL  56623104LL   // weight bf16 planes
__device__ float g_ws[59080704];

#define WTOT 2359296

// ---------------- helpers ----------------
__device__ __forceinline__ void fma2(ull &d, ull a, ull b) {
    asm("fma.rn.f32x2 %0, %1, %2, %0;" : "+l"(d) : "l"(a), "l"(b));
}
__device__ __forceinline__ ull mul2(ull a, ull b) {
    ull d; asm("mul.rn.f32x2 %0, %1, %2;" : "=l"(d) : "l"(a), "l"(b)); return d;
}
__device__ __forceinline__ ull pk2(float v) {
    ull r; unsigned u = __float_as_uint(v);
    asm("mov.b64 %0, {%1, %1};" : "=l"(r) : "r"(u));
    return r;
}
__device__ __forceinline__ float lo2(ull p) { return __uint_as_float((unsigned)p); }
__device__ __forceinline__ float hi2(ull p) { return __uint_as_float((unsigned)(p >> 32)); }

__device__ __forceinline__ unsigned pack_hl(float v) {
    __nv_bfloat16 h = __float2bfloat16(v);
    float hf = __bfloat162float(h);
    __nv_bfloat16 l = __float2bfloat16(v - hf);
    return (unsigned)__bfloat16_as_ushort(h) | ((unsigned)__bfloat16_as_ushort(l) << 16);
}
__device__ __forceinline__ unsigned prmt(unsigned a, unsigned b, unsigned s) {
    unsigned d; asm("prmt.b32 %0,%1,%2,%3;" : "=r"(d) : "r"(a), "r"(b), "r"(s)); return d;
}
__device__ __forceinline__ void ldsm4(unsigned &r0, unsigned &r1, unsigned &r2, unsigned &r3,
                                      unsigned saddr) {
    asm volatile("ldmatrix.sync.aligned.m8n8.x4.shared.b16 {%0,%1,%2,%3}, [%4];"
        : "=r"(r0), "=r"(r1), "=r"(r2), "=r"(r3) : "r"(saddr));
}
__device__ __forceinline__ void mma16(float c[4], unsigned a0, unsigned a1, unsigned a2,
                                      unsigned a3, unsigned b0, unsigned b1) {
    asm volatile("mma.sync.aligned.m16n8k16.row.col.f32.bf16.bf16.f32 "
        "{%0,%1,%2,%3}, {%4,%5,%6,%7}, {%8,%9}, {%0,%1,%2,%3};"
        : "+f"(c[0]), "+f"(c[1]), "+f"(c[2]), "+f"(c[3])
        : "r"(a0), "r"(a1), "r"(a2), "r"(a3), "r"(b0), "r"(b1));
}
__device__ __forceinline__ void cpa16(void* dst, const void* src) {
    unsigned d = (unsigned)__cvta_generic_to_shared(dst);
    asm volatile("cp.async.cg.shared.global [%0], [%1], 16;" :: "r"(d), "l"(src));
}
__device__ __forceinline__ void cpa4(void* dst, const void* src) {
    unsigned d = (unsigned)__cvta_generic_to_shared(dst);
    asm volatile("cp.async.ca.shared.global [%0], [%1], 4;" :: "r"(d), "l"(src));
}
#define CP_COMMIT asm volatile("cp.async.commit_group;")
#define CP_WAIT0  asm volatile("cp.async.wait_group 0;")
#define CP_WAIT2  asm volatile("cp.async.wait_group 2;")
#define CP_WAIT3  asm volatile("cp.async.wait_group 3;")

// ---------------- prep kernels ----------------
struct PrepTab {
    const float* src[19];
    int dst[19], M[19], K[19], sm[19], sk[19];
};

__global__ __launch_bounds__(256) void prep_w(__nv_bfloat16* hi, PrepTab pt) {
    int sgi = blockIdx.z;
    int idx = blockIdx.x * 256 + threadIdx.x;
    int MK = pt.M[sgi] * pt.K[sgi];
    if (idx >= MK) return;
    int k = idx % pt.K[sgi];
    int m = idx / pt.K[sgi];
    float v = pt.src[sgi][(ll)m * pt.sm[sgi] + (ll)k * pt.sk[sgi]];
    __nv_bfloat16 h = __float2bfloat16(v);
    float hf = __bfloat162float(h);
    __nv_bfloat16 l = __float2bfloat16(v - hf);
    hi[pt.dst[sgi] + idx] = h;
    hi[WTOT + pt.dst[sgi] + idx] = l;
}

__global__ __launch_bounds__(256) void prep_x(const float* __restrict__ x,
                                              unsigned* __restrict__ xp) {
    int idx = blockIdx.x * 256 + threadIdx.x;
    int t = idx & 2047;
    int rest = idx >> 11;
    int c = rest % Cc, b = rest / Cc;
    xp[(ll)b * 1572864 + (ll)(c >> 1) * 4096 + 2 * t + (c & 1)] = pack_hl(x[idx]);
}

// ---------------- GEMM ----------------
enum { EPI_NONE = 0, EPI_TANH = 1, EPI_MIX = 2, EPI_DECAY = 3, EPI_SIG = 4 };

struct ZMap {
    ll a[12], b[12], o[12], x1[12], x2[12];
    int epi[12], Kz[12], ym[12];
};

__device__ __forceinline__ float apply_epi(float v, int epi, const float* p1,
                                           const float* x2, int m, int n, int N) {
    if (epi == EPI_TANH) {
        v = tanhf(v);
    } else if (epi == EPI_MIX) {
        v = x2[(ll)m * N + n] * (1.f + p1[m] + v);
    } else if (epi == EPI_DECAY) {
        float u = -(p1[m] + v);
        float sp = fmaxf(u, 0.f) + log1pf(expf(-fabsf(u)));
        v = expf(-expf(-sp - 0.5f));
    } else if (epi == EPI_SIG) {
        v = 1.f / (1.f + expf(-(p1[m] + v)));
    }
    return v;
}

// block tile 64 x 64, KC=32, 4-stage ring, 256 threads (8 warps: 2m x 4n), 3 CTAs/SM
__global__ __launch_bounds__(256, 3) void gemm_k(
    const __nv_bfloat16* __restrict__ Apl, ll Atot,
    const unsigned* __restrict__ Bpl,
    float* __restrict__ Ob, unsigned* __restrict__ Pb,
    int sOM, int sON, int N, int omode,
    const float* __restrict__ aux1, const float* __restrict__ aux2,
    ZMap zm)
{
    constexpr int MT = 2;
    constexpr int ABYTES = 64 * 80;
    constexpr int STG = 2 * ABYTES + 16 * 544;
    extern __shared__ char smem[];

    const int z = blockIdx.z;
    if ((int)blockIdx.y >= zm.ym[z]) return;
    const int K = zm.Kz[z];
    const __nv_bfloat16* Ahi = Apl + zm.a[z];
    const unsigned* Bg = Bpl + zm.b[z];
    const ll zo = zm.o[z];
    const float* p1 = aux1 ? aux1 + zm.x1[z] : (const float*)0;
    const float* x2 = aux2 ? aux2 + zm.x2[z] : (const float*)0;
    const int epi = zm.epi[z];

    const int tid = threadIdx.x;
    const int m0 = blockIdx.y * 64, n0 = blockIdx.x * 64;
    const int warp = tid >> 5, lane = tid & 31;
    const int qr = lane >> 2, qc = lane & 3;
    const int wm0 = (warp & 1) * 32;
    const int wn0 = (warp >> 1) * 16;
    const int rowW = 2 * N;

    unsigned sbase = (unsigned)__cvta_generic_to_shared(smem);

    auto issue = [&](int kt) {
        char* S = smem + (kt & 3) * STG;
        int k0 = kt * 32;
        {
            int am = tid >> 2, ae = (tid & 3) * 8;
            const __nv_bfloat16* s0 = Ahi + (ll)(m0 + am) * K + k0 + ae;
            char* d0 = S + am * 80 + ae * 2;
            cpa16(d0, s0);
            cpa16(d0 + ABYTES, s0 + Atot);
        }
        {
            int kp = tid >> 4, wo = (tid & 15) * 8;
            const unsigned* s = Bg + (ll)(k0 / 2 + kp) * rowW + n0 * 2 + wo;
            char* d = S + 2 * ABYTES + kp * 544 + wo * 4;
            cpa16(d, s); cpa16(d + 16, s + 4);
        }
    };

    float c[MT][2][4];
#pragma unroll
    for (int mt = 0; mt < MT; mt++)
#pragma unroll
        for (int nt = 0; nt < 2; nt++)
#pragma unroll
            for (int r = 0; r < 4; r++) c[mt][nt][r] = 0.f;

    const int nk = K >> 5;
    issue(0); CP_COMMIT;
    if (nk > 1) issue(1);
    CP_COMMIT;
    if (nk > 2) issue(2);
    CP_COMMIT;

    for (int kt = 0; kt < nk; kt++) {
        CP_WAIT2;
        __syncthreads();
        if (kt + 3 < nk) issue(kt + 3);
        CP_COMMIT;

        char* Sst = smem + (kt & 3) * STG;
        unsigned SAu = sbase + (kt & 3) * STG;
        char* Sb = Sst + 2 * ABYTES;

#pragma unroll
        for (int s = 0; s < 2; s++) {
            unsigned bh[2][2], bl[2][2];
#pragma unroll
            for (int nt = 0; nt < 2; nt++) {
                int n = wn0 + nt * 8 + qr;
                uint2 w01 = *(const uint2*)(Sb + (s * 8 + qc) * 544 + n * 8);
                uint2 w23 = *(const uint2*)(Sb + (s * 8 + qc + 4) * 544 + n * 8);
                bh[nt][0] = prmt(w01.x, w01.y, 0x5410); bl[nt][0] = prmt(w01.x, w01.y, 0x7632);
                bh[nt][1] = prmt(w23.x, w23.y, 0x5410); bl[nt][1] = prmt(w23.x, w23.y, 0x7632);
            }
#pragma unroll
            for (int mt = 0; mt < MT; mt++) {
                unsigned aaddr = SAu + (wm0 + mt * 16 + (lane & 15)) * 80 + (lane >> 4) * 16 + s * 32;
                unsigned h0, h1, h2, h3, l0, l1, l2, l3;
                ldsm4(h0, h1, h2, h3, aaddr);
                ldsm4(l0, l1, l2, l3, aaddr + ABYTES);
#pragma unroll
                for (int nt = 0; nt < 2; nt++) {
                    mma16(c[mt][nt], h0, h1, h2, h3, bh[nt][0], bh[nt][1]);
                    mma16(c[mt][nt], l0, l1, l2, l3, bh[nt][0], bh[nt][1]);
                    mma16(c[mt][nt], h0, h1, h2, h3, bl[nt][0], bl[nt][1]);
                }
            }
        }
    }

    const bool use_tr = (omode == 0) && (sON != 1);
    if (use_tr) __syncthreads();
    float* Tf = (float*)smem;

#pragma unroll
    for (int mt = 0; mt < MT; mt++) {
#pragma unroll
        for (int nt = 0; nt < 2; nt++) {
            int mL = wm0 + mt * 16 + qr;
            int nL = wn0 + nt * 8 + qc * 2;
            int mA = m0 + mL;
            int nA = n0 + nL;
            float v0 = apply_epi(c[mt][nt][0], epi, p1, x2, mA, nA, N);
            float v1 = apply_epi(c[mt][nt][1], epi, p1, x2, mA, nA + 1, N);
            float v2 = apply_epi(c[mt][nt][2], epi, p1, x2, mA + 8, nA, N);
            float v3 = apply_epi(c[mt][nt][3], epi, p1, x2, mA + 8, nA + 1, N);
            if (omode == 0) {
                if (sON == 1) {
                    float* O = Ob + zo;
                    *(float2*)(O + (ll)mA * sOM + nA)       = make_float2(v0, v1);
                    *(float2*)(O + (ll)(mA + 8) * sOM + nA) = make_float2(v2, v3);
                } else {
                    Tf[nL * 68 + mL]           = v0;
                    Tf[(nL + 1) * 68 + mL]     = v1;
                    Tf[nL * 68 + mL + 8]       = v2;
                    Tf[(nL + 1) * 68 + mL + 8] = v3;
                }
            } else {
                unsigned* P = Pb + zo;
                ll r0 = (ll)(mA >> 1) * rowW + (mA & 1);
                ll r1 = r0 + (ll)4 * rowW;
                P[r0 + 2 * nA]       = pack_hl(v0);
                P[r0 + 2 * (nA + 1)] = pack_hl(v1);
                P[r1 + 2 * nA]       = pack_hl(v2);
                P[r1 + 2 * (nA + 1)] = pack_hl(v3);
            }
        }
    }

    if (use_tr) {
        __syncthreads();
        float* O = Ob + zo;
#pragma unroll
        for (int p = 0; p < 4; p++) {
            int row = p * 16 + (tid >> 4);
            int c4 = (tid & 15) * 4;
            float4 v = *(float4*)&Tf[row * 68 + c4];
            *(float4*)(O + (ll)(n0 + row) * sON + m0 + c4) = v;
        }
    }
}

// ---------------- E1 ----------------
__global__ __launch_bounds__(256) void e1_k(
    const float* __restrict__ kc, const float* __restrict__ kl,
    const float* __restrict__ asig, float* __restrict__ am, float* __restrict__ bm)
{
    int gw = (int)((blockIdx.x * blockDim.x + threadIdx.x) >> 5);
    int lane = threadIdx.x & 31;
    ll base = (ll)gw * 64;
    float k1 = kc[base + lane]      + kl[base + lane];
    float k2 = kc[base + lane + 32] + kl[base + lane + 32];
    float ss = k1 * k1 + k2 * k2;
#pragma unroll
    for (int o = 16; o; o >>= 1) ss += __shfl_xor_sync(0xffffffffu, ss, o);
    float inv = 1.f / fmaxf(sqrtf(ss), 1e-12f);
    float n1 = k1 * inv, n2 = k2 * inv;
    am[base + lane]      = -n1;
    am[base + lane + 32] = -n2;
    bm[base + lane]      = n1 * asig[base + lane];
    bm[base + lane + 32] = n2 * asig[base + lane + 32];
}

// ---------------- WKV7: RS=4, cp.async 8-buffer ring (5 steps ahead) ----------------
#define RS 4
__global__ __launch_bounds__(64) void wkv7_k(const float* __restrict__ rin, float* __restrict__ y)
{
    int blk = blockIdx.x;
    int rs = blk & 3;
    int bh = blk >> 2;
    int b = bh / Hh, h = bh % Hh;
    ll base = (ll)b * Tt * Cc + (ll)h * 64;

    int tid = threadIdx.x;
    int lr = tid >> 2, jc = tid & 3;
    int i = rs * 16 + lr;
    int jb = jc << 4;

    __shared__ __align__(16) float sh[8][384];

    auto stage = [&](int tt) {
        float* sd = sh[tt & 7];
        ll off = base + (ll)tt * Cc;
#pragma unroll
        for (int q = 0; q < 6; q++)
            cpa4(&sd[q * 64 + tid], &rin[(ll)q * BTCll + off + tid]);
        CP_COMMIT;
    };

    stage(0);
    stage(1);
    stage(2);
    stage(3);
    stage(4);

    ull S2[8];
#pragma unroll
    for (int u = 0; u < 8; u++) S2[u] = 0ull;
    float sa = 0.f;

    for (int t = 0; t < Tt; t++) {
        // committed = 5+t; wait_group 3 -> groups <= t+1 complete (sb and sn ready)
        if (t + 5 < Tt) { CP_WAIT3; } else { CP_WAIT0; }
        __syncthreads();               // fences step t-1 reads before buffer (t-3)&7 reuse
        if (t + 5 < Tt) stage(t + 5);

        const float* sb = sh[t & 7];
        const float* sn = sh[(t + 1) & 7];
        float vi = sb[3 * 64 + i];
        ull vi2 = pk2(vi), sa2 = pk2(sa);

        const ulonglong2* wp = (const ulonglong2*)(sb + 1 * 64 + jb);
        const ulonglong2* kp = (const ulonglong2*)(sb + 2 * 64 + jb);
        const ulonglong2* bp = (const ulonglong2*)(sb + 5 * 64 + jb);
        const ulonglong2* rp = (const ulonglong2*)(sb + 0 * 64 + jb);

        // S = S*w + sa*b + vi*k
#pragma unroll
        for (int q = 0; q < 4; q++) {
            ulonglong2 wv = wp[q], kv = kp[q], bv = bp[q];
            ull d0 = mul2(vi2, kv.x);
            fma2(d0, sa2, bv.x);
            fma2(d0, S2[2 * q], wv.x);
            S2[2 * q] = d0;
            ull d1 = mul2(vi2, kv.y);
            fma2(d1, sa2, bv.y);
            fma2(d1, S2[2 * q + 1], wv.y);
            S2[2 * q + 1] = d1;
        }

        // y partials
        ull ya = 0ull, yb = 0ull;
#pragma unroll
        for (int q = 0; q < 4; q++) {
            ulonglong2 rv = rp[q];
            fma2(ya, S2[2 * q], rv.x);
            fma2(yb, S2[2 * q + 1], rv.y);
        }

        // sa partials for t+1
        const ulonglong2* ap = (const ulonglong2*)(sn + 4 * 64 + jb);
        ull za = 0ull, zb = 0ull;
#pragma unroll
        for (int q = 0; q < 4; q++) {
            ulonglong2 av = ap[q];
            fma2(za, S2[2 * q], av.x);
            fma2(zb, S2[2 * q + 1], av.y);
        }

        float yv = (lo2(ya) + hi2(ya)) + (lo2(yb) + hi2(yb));
        float sv = (lo2(za) + hi2(za)) + (lo2(zb) + hi2(zb));
        yv += __shfl_xor_sync(0xffffffffu, yv, 1);
        sv += __shfl_xor_sync(0xffffffffu, sv, 1);
        yv += __shfl_xor_sync(0xffffffffu, yv, 2);
        sv += __shfl_xor_sync(0xffffffffu, sv, 2);
        sa = sv;
        if (jc == 0)
            y[base + (ll)t * Cc + i] = yv;
    }
}

// ---------------- E2 (writes YG planes) ----------------
__global__ __launch_bounds__(768) void e2_k(
    const float* __restrict__ y,
    const float* __restrict__ rr, const float* __restrict__ kk, const float* __restrict__ vv,
    const float* __restrict__ gg, const float* __restrict__ faaaa,
    const float* __restrict__ lnw, unsigned* __restrict__ ygp)
{
    int bt = blockIdx.x;
    int b = bt >> 11, t = bt & 2047;
    ll base = (ll)bt * Cc;
    int c = threadIdx.x;
    int w = c >> 5, h = c >> 6, j = c & 63, lane = c & 31;
    float yv = y[base + c];
    float rv = rr[base + c], kv = kk[base + c], vV = vv[base + c];
    float s1 = yv * yv;
    float s2 = rv * kv * faaaa[h * 64 + j];
#pragma unroll
    for (int o = 16; o; o >>= 1) {
        s1 += __shfl_xor_sync(0xffffffffu, s1, o);
        s2 += __shfl_xor_sync(0xffffffffu, s2, o);
    }
    __shared__ float sh1[24], sh2[24];
    if (lane == 0) { sh1[w] = s1; sh2[w] = s2; }
    __syncthreads();
    float tot = 0.f;
#pragma unroll
    for (int q = 0; q < 24; q++) tot += sh1[q];
    float scale = rsqrtf(tot * (1.f / 768.f) + 1e-5f);
    float rk = sh2[h * 2] + sh2[h * 2 + 1];
    float yo = (yv * scale * lnw[c] + rk * vV) * gg[base + c];
    ygp[(ll)b * 1572864 + (ll)(c >> 1) * 4096 + 2 * t + (c & 1)] = pack_hl(yo);
}

// ---------------- launch ----------------
#define SMEM64 (4 * (2 * 64 * 80 + 16 * 544))

extern "C" void kernel_launch(void* const* d_in, const int* in_sizes, int n_in,
                              void* d_out, int out_size)
{
    (void)in_sizes; (void)n_in; (void)out_size;
    const float* x       = (const float*)d_in[0];
    const float* tmaa_r  = (const float*)d_in[2];
    const float* tmaa_w  = (const float*)d_in[3];
    const float* tmaa_k  = (const float*)d_in[4];
    const float* tmaa_v  = (const float*)d_in[5];
    const float* tmaa_a  = (const float*)d_in[6];
    const float* tmaa_g  = (const float*)d_in[7];
    const float* tdecay  = (const float*)d_in[8];
    const float* faaaa   = (const float*)d_in[9];
    const float* taaaaa  = (const float*)d_in[10];
    const float* maa_w1  = (const float*)d_in[11];
    const float* maa_w2  = (const float*)d_in[12];
    const float* dec_w1  = (const float*)d_in[13];
    const float* dec_w2  = (const float*)d_in[14];
    const float* aaa_w1  = (const float*)d_in[15];
    const float* aaa_w2  = (const float*)d_in[16];
    const float* kkk_w1  = (const float*)d_in[17];
    const float* kkk_w2  = (const float*)d_in[18];
    const float* gate_w1 = (const float*)d_in[19];
    const float* gate_w2 = (const float*)d_in[20];
    const float* w_key   = (const float*)d_in[21];
    const float* w_val   = (const float*)d_in[22];
    const float* w_rec   = (const float*)d_in[23];
    const float* w_out   = (const float*)d_in[24];
    const float* lnw     = (const float*)d_in[25];
    float* out = (float*)d_out;

    static int attr_done = 0;
    if (!attr_done) {
        cudaFuncSetAttribute(gemm_k, cudaFuncAttributeMaxDynamicSharedMemorySize, SMEM64);
        attr_done = 1;
    }

    float* ws = 0;
    cudaGetSymbolAddress((void**)&ws, g_ws);

    unsigned* XP   = (unsigned*)(ws + WS_XP);
    unsigned* TMP  = (unsigned*)(ws + WS_TMP);
    unsigned* XBP  = (unsigned*)(ws + WS_XBP);
    float* RIN = ws + WS_RIN;
    float* Y   = ws + WS_Y;
    __nv_bfloat16* WPL = (__nv_bfloat16*)(ws + WS_WPL);

    // ---- weight prep ----
    {
        PrepTab pt;
        int i = 0;
        auto seg = [&](const float* s, int d, int M, int K, int sm, int sk) {
            pt.src[i] = s; pt.dst[i] = d; pt.M[i] = M; pt.K[i] = K; pt.sm[i] = sm; pt.sk[i] = sk; i++;
        };
        seg(maa_w1, 0, 384, 768, 768, 1);
        for (int n = 0; n < 6; n++) seg(maa_w2 + n * 49152, 294912 + n * 49152, 768, 64, 1, 768);
        seg(w_rec, 589824, 768, 384, 384, 1);
        seg(w_key, 884736, 768, 384, 384, 1);
        seg(w_val, 1179648, 768, 384, 384, 1);
        seg(dec_w1, 1474560, 64, 768, 768, 1);
        seg(kkk_w1, 1523712, 64, 768, 768, 1);
        seg(aaa_w1, 1572864, 64, 768, 768, 1);
        seg(dec_w2, 1622016, 768, 64, 64, 1);
        seg(kkk_w2, 1671168, 768, 64, 64, 1);
        seg(aaa_w2, 1720320, 768, 64, 64, 1);
        seg(gate_w1, 1769472, 192, 768, 768, 1);
        seg(gate_w2, 1916928, 768, 192, 192, 1);
        seg(w_out, 2064384, 768, 384, 384, 1);
        prep_w<<<dim3(1152, 1, 19), 256>>>(WPL, pt);
    }
    prep_x<<<(Bb * Cc * Tt) / 256, 256>>>(x, XP);

    // G1) TM planes = tanh(maa_w1 @ x): M=384, K=768
    {
        ZMap zm = {};
        for (int b = 0; b < 2; b++) {
            zm.b[b] = (ll)b * 1572864;
            zm.o[b] = (ll)b * 786432;
            zm.epi[b] = EPI_TANH;
            zm.Kz[b] = 768; zm.ym[b] = 6;
        }
        gemm_k<<<dim3(32, 6, 2), 256, SMEM64>>>(WPL, WTOT, XP, 0, TMP,
                                                0, 0, 2048, 1, 0, 0, zm);
    }

    // G2) MIX -> XB planes: z=n*2+b, M=768, K=64
    {
        ZMap zm = {};
        const float* tmaas[6] = {tmaa_r, tmaa_w, tmaa_k, tmaa_v, tmaa_a, tmaa_g};
        for (int n = 0; n < 6; n++)
            for (int b = 0; b < 2; b++) {
                int z = n * 2 + b;
                zm.a[z]  = 294912 + (ll)n * 49152;
                zm.b[z]  = (ll)b * 786432 + (ll)n * 131072;
                zm.o[z]  = ((ll)n * 2 + b) * 1572864;
                zm.x1[z] = (ll)(tmaas[n] - tmaa_r);
                zm.x2[z] = (ll)b * CTll;
                zm.epi[z] = EPI_MIX;
                zm.Kz[z] = 64; zm.ym[z] = 12;
            }
        gemm_k<<<dim3(32, 12, 12), 256, SMEM64>>>(WPL, WTOT, TMP, 0, XBP,
                                                  0, 0, 2048, 1, tmaa_r, x, zm);
    }

    // G3) convs (r,k,v) -> RIN fp32: z=q*4+g*2+b, M=384, K=384 (transposed store)
    {
        ZMap zm = {};
        const int xbi[3] = {0, 2, 3};
        const int rio[3] = {0, 2, 3};
        for (int q = 0; q < 3; q++)
            for (int g = 0; g < 2; g++)
                for (int b = 0; b < 2; b++) {
                    int z = q * 4 + g * 2 + b;
                    zm.a[z] = 589824 + (ll)q * 294912 + (ll)g * 147456;
                    zm.b[z] = ((ll)xbi[q] * 2 + b) * 1572864 + (ll)g * 786432;
                    zm.o[z] = (ll)rio[q] * BTCll + (ll)b * CTll + g * 384;
                    zm.epi[z] = EPI_NONE;
                    zm.Kz[z] = 384; zm.ym[z] = 6;
                }
        gemm_k<<<dim3(32, 6, 12), 256, SMEM64>>>(WPL, WTOT, XBP, RIN, 0,
                                                 1, Cc, 2048, 0, 0, 0, zm);
    }

    // G45) lora stage1 (dec,kkk,aaa) + gate stage1, merged: K=768
    {
        ZMap zm = {};
        const int sl[3] = {1, 2, 4};
        for (int q = 0; q < 3; q++)
            for (int b = 0; b < 2; b++) {
                int z = q * 2 + b;
                zm.a[z] = 1474560 + (ll)q * 49152;
                zm.b[z] = ((ll)sl[q] * 2 + b) * 1572864;
                zm.o[z] = WS_H1P + ((ll)q * 2 + b) * 131072;
                zm.epi[z] = EPI_TANH;
                zm.Kz[z] = 768; zm.ym[z] = 1;
            }
        for (int b = 0; b < 2; b++) {
            int z = 6 + b;
            zm.a[z] = 1769472;
            zm.b[z] = (10LL + b) * 1572864;
            zm.o[z] = WS_TM2P + (ll)b * 393216;
            zm.epi[z] = EPI_TANH;
            zm.Kz[z] = 768; zm.ym[z] = 3;
        }
        gemm_k<<<dim3(32, 3, 8), 256, SMEM64>>>(WPL, WTOT, XBP, 0, (unsigned*)ws,
                                                0, 0, 2048, 1, 0, 0, zm);
    }

    // G67) lora stage2 (wdec, KL, AS) + gate stage2, merged (transposed store)
    {
        ZMap zm = {};
        ll od[3] = {WS_RIN + BTCll, WS_KL, WS_AS};
        const int ep[3] = {EPI_DECAY, EPI_NONE, EPI_SIG};
        ll xd[3] = {0, 0, (ll)(taaaaa - tdecay)};
        for (int q = 0; q < 3; q++)
            for (int b = 0; b < 2; b++) {
                int z = q * 2 + b;
                zm.a[z]  = 1622016 + (ll)q * 49152;
                zm.b[z]  = WS_H1P + ((ll)q * 2 + b) * 131072;
                zm.o[z]  = od[q] + (ll)b * CTll;
                zm.x1[z] = xd[q];
                zm.epi[z] = ep[q];
                zm.Kz[z] = 64; zm.ym[z] = 12;
            }
        for (int b = 0; b < 2; b++) {
            int z = 6 + b;
            zm.a[z] = 1916928;
            zm.b[z] = WS_TM2P + (ll)b * 393216;
            zm.o[z] = WS_GT + (ll)b * CTll;
            zm.epi[z] = EPI_NONE;
            zm.Kz[z] = 192; zm.ym[z] = 12;
        }
        gemm_k<<<dim3(32, 12, 8), 256, SMEM64>>>(WPL, WTOT, (unsigned*)ws, ws, 0,
                                                 1, Cc, 2048, 0, tdecay, 0, zm);
    }

    // E1
    e1_k<<<(Bb * Tt * Hh) / 8, 256>>>(RIN + 2 * BTCll, ws + WS_KL, ws + WS_AS,
                                      RIN + 4 * BTCll, RIN + 5 * BTCll);

    // WKV7
    wkv7_k<<<Bb * Hh * RS, 64>>>(RIN, Y);

    // E2 -> YG planes (reuse XP)
    e2_k<<<Bb * Tt, 768>>>(Y, RIN, RIN + 2 * BTCll, RIN + 3 * BTCll,
                           ws + WS_GT, faaaa, lnw, XP);

    // G11) output conv: z=g*2+b, M=384, K=384, out fp32 (B,C,T)
    {
        ZMap zm = {};
        for (int g = 0; g < 2; g++)
            for (int b = 0; b < 2; b++) {
                int z = g * 2 + b;
                zm.a[z] = 2064384 + (ll)g * 147456;
                zm.b[z] = (ll)b * 1572864 + (ll)g * 786432;
                zm.o[z] = (ll)b * CTll + (ll)g * 384 * Tt;
                zm.epi[z] = EPI_NONE;
                zm.Kz[z] = 384; zm.ym[z] = 6;
            }
        gemm_k<<<dim3(32, 6, 4), 256, SMEM64>>>(WPL, WTOT, XP, out, 0,
                                                Tt, 1, 2048, 0, 0, 0, zm);
    }
}